// round 3
// baseline (speedup 1.0000x reference)
#include <cuda_runtime.h>
#include <math.h>

#define B_   2
#define NQ_  2048
#define NKV_ 2048
#define D_   1024
#define H_   16
#define DH_  64

// Scratch (allocation-free): projected Q/K/V and attention output
__device__ float g_Qp[B_ * NQ_ * D_];
__device__ float g_Kp[B_ * NKV_ * D_];
__device__ float g_Vp[B_ * NKV_ * D_];
__device__ float g_Op[B_ * NQ_ * D_];

// ---------------------------------------------------------------------------
// C[M,N] = A[M,K] @ W[N,K]^T + bias[N]     (torch Linear, NT layout)
// 128x128 tile, BK=8, 256 threads, 8x8 micro-tile with split 4+4 layout.
// ---------------------------------------------------------------------------
__global__ __launch_bounds__(256) void gemm_nt_bias(
    const float* __restrict__ A, const float* __restrict__ W,
    const float* __restrict__ bias, float* __restrict__ C,
    int M, int N, int K)
{
    __shared__ float As[8][128];
    __shared__ float Bs[8][128];

    const int tid = threadIdx.x;
    const int bm  = blockIdx.y * 128;
    const int bn  = blockIdx.x * 128;

    const int lr = tid >> 1;            // 0..127 tile row
    const int lk = (tid & 1) << 2;      // 0 or 4
    const int tx = tid & 15;            // micro-tile col group
    const int ty = tid >> 4;            // micro-tile row group

    float acc[8][8];
#pragma unroll
    for (int i = 0; i < 8; i++)
#pragma unroll
        for (int j = 0; j < 8; j++) acc[i][j] = 0.f;

    const float* Aptr = A + (long)(bm + lr) * K + lk;
    const float* Wptr = W + (long)(bn + lr) * K + lk;

    for (int k0 = 0; k0 < K; k0 += 8) {
        float4 av = *(const float4*)(Aptr + k0);
        float4 wv = *(const float4*)(Wptr + k0);
        As[lk + 0][lr] = av.x;
        As[lk + 1][lr] = av.y;
        As[lk + 2][lr] = av.z;
        As[lk + 3][lr] = av.w;
        Bs[lk + 0][lr] = wv.x;
        Bs[lk + 1][lr] = wv.y;
        Bs[lk + 2][lr] = wv.z;
        Bs[lk + 3][lr] = wv.w;
        __syncthreads();

#pragma unroll
        for (int kk = 0; kk < 8; kk++) {
            float a[8], b[8];
            *(float4*)(a)     = *(const float4*)&As[kk][ty * 4];
            *(float4*)(a + 4) = *(const float4*)&As[kk][64 + ty * 4];
            *(float4*)(b)     = *(const float4*)&Bs[kk][tx * 4];
            *(float4*)(b + 4) = *(const float4*)&Bs[kk][64 + tx * 4];
#pragma unroll
            for (int i = 0; i < 8; i++)
#pragma unroll
                for (int j = 0; j < 8; j++)
                    acc[i][j] = fmaf(a[i], b[j], acc[i][j]);
        }
        __syncthreads();
    }

    // Epilogue: bias add + store (two 4-wide column groups, two 4-row groups)
#pragma unroll
    for (int ih = 0; ih < 2; ih++) {
#pragma unroll
        for (int i = 0; i < 4; i++) {
            const int r = bm + ih * 64 + ty * 4 + i;
#pragma unroll
            for (int jh = 0; jh < 2; jh++) {
                const int c = bn + jh * 64 + tx * 4;
                const float4 bv = *(const float4*)&bias[c];
                float4 o;
                o.x = acc[ih * 4 + i][jh * 4 + 0] + bv.x;
                o.y = acc[ih * 4 + i][jh * 4 + 1] + bv.y;
                o.z = acc[ih * 4 + i][jh * 4 + 2] + bv.z;
                o.w = acc[ih * 4 + i][jh * 4 + 3] + bv.w;
                *(float4*)&C[(long)r * N + c] = o;
            }
        }
    }
}

// ---------------------------------------------------------------------------
// Flash attention, fp32. One thread owns one q-row (fully independent online
// softmax, no cross-thread reductions). BM=64 q rows / block (64 threads),
// BN=32 kv rows per tile, d_h = 64.
// Layout of Q/K/V: [B*N, D] row-major, head slice at column h*64.
// ---------------------------------------------------------------------------
#define FBM 64
#define FBN 32

__global__ __launch_bounds__(64) void flash_kernel(
    const float* __restrict__ Q, const float* __restrict__ K,
    const float* __restrict__ V, float* __restrict__ O)
{
    __shared__ float Qs[FBM][DH_ + 4];
    __shared__ float Ks[FBN][DH_ + 4];
    __shared__ float Vs[FBN][DH_ + 4];

    const int tid = threadIdx.x;      // 0..63  == q row within tile == column on loads
    const int qt  = blockIdx.x;       // q tile
    const int h   = blockIdx.y;       // head
    const int b   = blockIdx.z;       // batch

    const long qbase = ((long)(b * NQ_ + qt * FBM)) * D_ + h * DH_;

    // Load Q tile (coalesced: 64 threads load one 256B row per iteration)
#pragma unroll 4
    for (int r = 0; r < FBM; r++)
        Qs[r][tid] = Q[qbase + (long)r * D_ + tid];

    float m = -1e30f, l = 0.f;
    float acc[DH_];
#pragma unroll
    for (int d = 0; d < DH_; d++) acc[d] = 0.f;

    const float scale = 0.125f;  // 1/sqrt(64)
    const long kvb0 = ((long)(b * NKV_)) * D_ + h * DH_;

    for (int kt = 0; kt < NKV_ / FBN; kt++) {
        __syncthreads();  // previous tile's compute done (also covers Q load)
        const long kb = kvb0 + (long)kt * FBN * D_;
#pragma unroll 4
        for (int r = 0; r < FBN; r++) {
            Ks[r][tid] = K[kb + (long)r * D_ + tid];
            Vs[r][tid] = V[kb + (long)r * D_ + tid];
        }
        __syncthreads();

        // s = q_row . K_j  (K rows broadcast across the 64 threads)
        float s[FBN];
#pragma unroll
        for (int j = 0; j < FBN; j++) s[j] = 0.f;
#pragma unroll 4
        for (int k4 = 0; k4 < DH_ / 4; k4++) {
            const float4 q4 = *(const float4*)&Qs[tid][k4 * 4];
#pragma unroll
            for (int j = 0; j < FBN; j++) {
                const float4 kk = *(const float4*)&Ks[j][k4 * 4];
                s[j] = fmaf(q4.x, kk.x, s[j]);
                s[j] = fmaf(q4.y, kk.y, s[j]);
                s[j] = fmaf(q4.z, kk.z, s[j]);
                s[j] = fmaf(q4.w, kk.w, s[j]);
            }
        }

        // online softmax update (per-thread, no communication)
        float tmax = -1e30f;
#pragma unroll
        for (int j = 0; j < FBN; j++) {
            s[j] *= scale;
            tmax = fmaxf(tmax, s[j]);
        }
        const float mnew = fmaxf(m, tmax);
        const float corr = __expf(m - mnew);
        float psum = 0.f;
#pragma unroll
        for (int j = 0; j < FBN; j++) {
            s[j] = __expf(s[j] - mnew);
            psum += s[j];
        }
        l = l * corr + psum;
        m = mnew;

#pragma unroll
        for (int d = 0; d < DH_; d++) acc[d] *= corr;

        // acc += p_j * V_j
#pragma unroll
        for (int j = 0; j < FBN; j++) {
            const float pj = s[j];
#pragma unroll
            for (int d4 = 0; d4 < DH_ / 4; d4++) {
                const float4 v4 = *(const float4*)&Vs[j][d4 * 4];
                acc[d4 * 4 + 0] = fmaf(pj, v4.x, acc[d4 * 4 + 0]);
                acc[d4 * 4 + 1] = fmaf(pj, v4.y, acc[d4 * 4 + 1]);
                acc[d4 * 4 + 2] = fmaf(pj, v4.z, acc[d4 * 4 + 2]);
                acc[d4 * 4 + 3] = fmaf(pj, v4.w, acc[d4 * 4 + 3]);
            }
        }
    }

    // Normalize and store this thread's q row
    const float inv = 1.f / l;
    const long ob = qbase + (long)tid * D_;
#pragma unroll
    for (int d4 = 0; d4 < DH_ / 4; d4++) {
        float4 o;
        o.x = acc[d4 * 4 + 0] * inv;
        o.y = acc[d4 * 4 + 1] * inv;
        o.z = acc[d4 * 4 + 2] * inv;
        o.w = acc[d4 * 4 + 3] * inv;
        *(float4*)&O[ob + d4 * 4] = o;
    }
}

// ---------------------------------------------------------------------------
extern "C" void kernel_launch(void* const* d_in, const int* in_sizes, int n_in,
                              void* d_out, int out_size)
{
    const float* q  = (const float*)d_in[0];
    const float* kv = (const float*)d_in[1];
    const float* Wq = (const float*)d_in[2];
    const float* bq = (const float*)d_in[3];
    const float* Wk = (const float*)d_in[4];
    const float* bk = (const float*)d_in[5];
    const float* Wv = (const float*)d_in[6];
    const float* bv = (const float*)d_in[7];
    const float* Wo = (const float*)d_in[8];
    const float* bo = (const float*)d_in[9];
    float* out = (float*)d_out;

    float *Qp, *Kp, *Vp, *Op;
    cudaGetSymbolAddress((void**)&Qp, g_Qp);
    cudaGetSymbolAddress((void**)&Kp, g_Kp);
    cudaGetSymbolAddress((void**)&Vp, g_Vp);
    cudaGetSymbolAddress((void**)&Op, g_Op);

    const int M = B_ * NQ_;   // 4096
    dim3 ggrid(D_ / 128, M / 128);  // (8, 32)

    gemm_nt_bias<<<ggrid, 256>>>(q,  Wq, bq, Qp, M, D_, D_);
    gemm_nt_bias<<<ggrid, 256>>>(kv, Wk, bk, Kp, M, D_, D_);
    gemm_nt_bias<<<ggrid, 256>>>(kv, Wv, bv, Vp, M, D_, D_);

    flash_kernel<<<dim3(NQ_ / FBM, H_, B_), 64>>>(Qp, Kp, Vp, Op);

    gemm_nt_bias<<<ggrid, 256>>>(Op, Wo, bo, out, M, D_, D_);
}

// round 5
// speedup vs baseline: 1.1512x; 1.1512x over previous
#include <cuda_runtime.h>
#include <cuda_bf16.h>
#include <math.h>
#include <stdint.h>

#define B_   2
#define NQ_  2048
#define NKV_ 2048
#define D_   1024
#define H_   16
#define DH_  64

// Scratch (allocation-free)
__device__ float g_Qp[B_ * NQ_ * D_];
__device__ float g_Kp[B_ * NKV_ * D_];
__device__ float g_Vp[B_ * NKV_ * D_];
__device__ float g_Op[B_ * NQ_ * D_];

__device__ __forceinline__ uint32_t smem_u32(const void* p) {
    uint32_t a;
    asm("{ .reg .u64 t; cvta.to.shared.u64 t, %1; cvt.u32.u64 %0, t; }"
        : "=r"(a) : "l"(p));
    return a;
}

// m16n8k16 row.col bf16 MMA (sm_80+ PTX — no 'a'-target features needed)
__device__ __forceinline__ void mma_bf16(float* d, const uint32_t* a,
                                         uint32_t b0, uint32_t b1) {
    asm volatile(
        "mma.sync.aligned.m16n8k16.row.col.f32.bf16.bf16.f32 "
        "{%0,%1,%2,%3}, {%4,%5,%6,%7}, {%8,%9}, {%0,%1,%2,%3};"
        : "+f"(d[0]), "+f"(d[1]), "+f"(d[2]), "+f"(d[3])
        : "r"(a[0]), "r"(a[1]), "r"(a[2]), "r"(a[3]), "r"(b0), "r"(b1));
}

__device__ __forceinline__ void ldmx4(uint32_t* r, uint32_t addr) {
    asm volatile(
        "ldmatrix.sync.aligned.m8n8.x4.shared.b16 {%0,%1,%2,%3}, [%4];"
        : "=r"(r[0]), "=r"(r[1]), "=r"(r[2]), "=r"(r[3]) : "r"(addr));
}

// ===========================================================================
// HMMA GEMM: C[4096,1024] = A[4096,1024] @ W[1024,1024]^T + bias
// bf16x3 split precision. CTA tile 128x128, K-chunk 64, 256 threads (8 warps
// as 4(M) x 2(N); warp tile 32x64). fp32 staged via cp.async, converted
// in-smem to hi/lo bf16 tiles (pitch 144B, ldmatrix conflict-free).
// ===========================================================================
#define GM 4096
#define GN 1024
#define GK 1024

#define PITCH_B  144                     // bytes per tile row (72 bf16)
#define TILE_B   (128 * PITCH_B)         // 18432
#define SM_STAGE_A 0                     // 128x64 fp32 = 32768
#define SM_STAGE_W 32768
#define SM_AHI   65536
#define SM_ALO   (SM_AHI + TILE_B)
#define SM_WHI   (SM_AHI + 2 * TILE_B)
#define SM_WLO   (SM_AHI + 3 * TILE_B)
#define SM_TOTAL (SM_AHI + 4 * TILE_B)   // 139264 bytes

__global__ __launch_bounds__(256) void gemm_mma(
    const float* __restrict__ A, const float* __restrict__ W,
    const float* __restrict__ bias, float* __restrict__ C)
{
    extern __shared__ char smem[];
    const uint32_t sb = smem_u32(smem);
    const int tid  = threadIdx.x;
    const int wid  = tid >> 5;
    const int lane = tid & 31;
    const int bm = blockIdx.y * 128;
    const int bn = blockIdx.x * 128;
    const int warp_m = wid >> 1;         // 0..3
    const int warp_n = wid & 1;          // 0..1

    float acc[2][8][4];
#pragma unroll
    for (int i = 0; i < 2; i++)
#pragma unroll
        for (int j = 0; j < 8; j++)
#pragma unroll
            for (int k = 0; k < 4; k++) acc[i][j][k] = 0.f;

    // ---- cp.async stage of chunk `c` (128x64 fp32 of A and W) ----
    auto issue_chunk = [&](int chunk) {
        const int kc = chunk * 64;
#pragma unroll
        for (int it = 0; it < 8; it++) {
            const int idx = it * 256 + tid;
            const int r  = idx >> 4;           // 0..127
            const int c4 = idx & 15;           // float4 index
            const uint32_t da = sb + SM_STAGE_A + (uint32_t)((r * 64 + c4 * 4) * 4);
            const float* sa = A + (long)(bm + r) * GK + kc + c4 * 4;
            asm volatile("cp.async.cg.shared.global [%0], [%1], 16;" :: "r"(da), "l"(sa));
            const uint32_t dw = sb + SM_STAGE_W + (uint32_t)((r * 64 + c4 * 4) * 4);
            const float* sw = W + (long)(bn + r) * GK + kc + c4 * 4;
            asm volatile("cp.async.cg.shared.global [%0], [%1], 16;" :: "r"(dw), "l"(sw));
        }
        asm volatile("cp.async.commit_group;" ::: "memory");
    };

    issue_chunk(0);

    for (int chunk = 0; chunk < GK / 64; chunk++) {
        asm volatile("cp.async.wait_group 0;" ::: "memory");
        __syncthreads();   // stage ready AND previous compute done

        // ---- convert fp32 stage -> hi/lo bf16 tiles ----
#pragma unroll
        for (int it = 0; it < 8; it++) {
            const int idx = it * 256 + tid;
            const int r  = idx >> 4;
            const int c4 = idx & 15;
            const float4 va = *(const float4*)(smem + SM_STAGE_A + (r * 64 + c4 * 4) * 4);
            const float4 vw = *(const float4*)(smem + SM_STAGE_W + (r * 64 + c4 * 4) * 4);
            const uint32_t toff = (uint32_t)(r * PITCH_B + c4 * 8);

            {
                __nv_bfloat16 h0 = __float2bfloat16(va.x), h1 = __float2bfloat16(va.y);
                __nv_bfloat16 h2 = __float2bfloat16(va.z), h3 = __float2bfloat16(va.w);
                __nv_bfloat16 l0 = __float2bfloat16(va.x - __bfloat162float(h0));
                __nv_bfloat16 l1 = __float2bfloat16(va.y - __bfloat162float(h1));
                __nv_bfloat16 l2 = __float2bfloat16(va.z - __bfloat162float(h2));
                __nv_bfloat16 l3 = __float2bfloat16(va.w - __bfloat162float(h3));
                __nv_bfloat162 hp0, hp1, lp0, lp1;
                hp0.x = h0; hp0.y = h1; hp1.x = h2; hp1.y = h3;
                lp0.x = l0; lp0.y = l1; lp1.x = l2; lp1.y = l3;
                uint2 hv, lv;
                hv.x = *(uint32_t*)&hp0; hv.y = *(uint32_t*)&hp1;
                lv.x = *(uint32_t*)&lp0; lv.y = *(uint32_t*)&lp1;
                *(uint2*)(smem + SM_AHI + toff) = hv;
                *(uint2*)(smem + SM_ALO + toff) = lv;
            }
            {
                __nv_bfloat16 h0 = __float2bfloat16(vw.x), h1 = __float2bfloat16(vw.y);
                __nv_bfloat16 h2 = __float2bfloat16(vw.z), h3 = __float2bfloat16(vw.w);
                __nv_bfloat16 l0 = __float2bfloat16(vw.x - __bfloat162float(h0));
                __nv_bfloat16 l1 = __float2bfloat16(vw.y - __bfloat162float(h1));
                __nv_bfloat16 l2 = __float2bfloat16(vw.z - __bfloat162float(h2));
                __nv_bfloat16 l3 = __float2bfloat16(vw.w - __bfloat162float(h3));
                __nv_bfloat162 hp0, hp1, lp0, lp1;
                hp0.x = h0; hp0.y = h1; hp1.x = h2; hp1.y = h3;
                lp0.x = l0; lp0.y = l1; lp1.x = l2; lp1.y = l3;
                uint2 hv, lv;
                hv.x = *(uint32_t*)&hp0; hv.y = *(uint32_t*)&hp1;
                lv.x = *(uint32_t*)&lp0; lv.y = *(uint32_t*)&lp1;
                *(uint2*)(smem + SM_WHI + toff) = hv;
                *(uint2*)(smem + SM_WLO + toff) = lv;
            }
        }
        __syncthreads();   // tiles ready; stage free for next prefetch

        if (chunk + 1 < GK / 64) issue_chunk(chunk + 1);

        // ---- compute: 4 K=16 steps ----
#pragma unroll
        for (int ks = 0; ks < 4; ks++) {
            uint32_t ah[2][4], al[2][4];
#pragma unroll
            for (int mt = 0; mt < 2; mt++) {
                const uint32_t ra = (uint32_t)((warp_m * 32 + mt * 16 + (lane & 15)) * PITCH_B
                                  + ks * 32 + (lane >> 4) * 16);
                ldmx4(ah[mt], sb + SM_AHI + ra);
                ldmx4(al[mt], sb + SM_ALO + ra);
            }
            uint32_t bh[4][4], bl[4][4];
#pragma unroll
            for (int nt2 = 0; nt2 < 4; nt2++) {
                const uint32_t rb = (uint32_t)((warp_n * 64 + nt2 * 16 + (lane & 15)) * PITCH_B
                                  + ks * 32 + (lane >> 4) * 16);
                ldmx4(bh[nt2], sb + SM_WHI + rb);
                ldmx4(bl[nt2], sb + SM_WLO + rb);
            }
#pragma unroll
            for (int mt = 0; mt < 2; mt++) {
#pragma unroll
                for (int nt = 0; nt < 8; nt++) {
                    const int g = nt >> 1, o = nt & 1;
                    const uint32_t b0h = bh[g][o], b1h = bh[g][o + 2];
                    const uint32_t b0l = bl[g][o], b1l = bl[g][o + 2];
                    mma_bf16(acc[mt][nt], ah[mt], b0h, b1h);   // hi*hi
                    mma_bf16(acc[mt][nt], ah[mt], b0l, b1l);   // hi*lo
                    mma_bf16(acc[mt][nt], al[mt], b0h, b1h);   // lo*hi
                }
            }
        }
        __syncthreads();   // compute done before next convert overwrites tiles
    }

    // ---- epilogue: bias add + store ----
    const int rq = lane >> 2;            // 0..7
    const int cq = (lane & 3) * 2;       // 0,2,4,6
#pragma unroll
    for (int mt = 0; mt < 2; mt++) {
        const int r0 = bm + warp_m * 32 + mt * 16 + rq;
#pragma unroll
        for (int nt = 0; nt < 8; nt++) {
            const int c = bn + warp_n * 64 + nt * 8 + cq;
            const float2 bv = *(const float2*)&bias[c];
            float2 o0, o1;
            o0.x = acc[mt][nt][0] + bv.x;
            o0.y = acc[mt][nt][1] + bv.y;
            o1.x = acc[mt][nt][2] + bv.x;
            o1.y = acc[mt][nt][3] + bv.y;
            *(float2*)&C[(long)r0 * GN + c] = o0;
            *(float2*)&C[(long)(r0 + 8) * GN + c] = o1;
        }
    }
}

// ===========================================================================
// Flash attention fp32 (unchanged — passing since R0)
// ===========================================================================
#define FBM 64
#define FBN 32

__global__ __launch_bounds__(64) void flash_kernel(
    const float* __restrict__ Q, const float* __restrict__ K,
    const float* __restrict__ V, float* __restrict__ O)
{
    __shared__ float Qs[FBM][DH_ + 4];
    __shared__ float Ks[FBN][DH_ + 4];
    __shared__ float Vs[FBN][DH_ + 4];

    const int tid = threadIdx.x;
    const int qt  = blockIdx.x;
    const int h   = blockIdx.y;
    const int b   = blockIdx.z;

    const long qbase = ((long)(b * NQ_ + qt * FBM)) * D_ + h * DH_;

#pragma unroll 4
    for (int r = 0; r < FBM; r++)
        Qs[r][tid] = Q[qbase + (long)r * D_ + tid];

    float m = -1e30f, l = 0.f;
    float acc[DH_];
#pragma unroll
    for (int d = 0; d < DH_; d++) acc[d] = 0.f;

    const float scale = 0.125f;
    const long kvb0 = ((long)(b * NKV_)) * D_ + h * DH_;

    for (int kt = 0; kt < NKV_ / FBN; kt++) {
        __syncthreads();
        const long kb = kvb0 + (long)kt * FBN * D_;
#pragma unroll 4
        for (int r = 0; r < FBN; r++) {
            Ks[r][tid] = K[kb + (long)r * D_ + tid];
            Vs[r][tid] = V[kb + (long)r * D_ + tid];
        }
        __syncthreads();

        float s[FBN];
#pragma unroll
        for (int j = 0; j < FBN; j++) s[j] = 0.f;
#pragma unroll 4
        for (int k4 = 0; k4 < DH_ / 4; k4++) {
            const float4 q4 = *(const float4*)&Qs[tid][k4 * 4];
#pragma unroll
            for (int j = 0; j < FBN; j++) {
                const float4 kk = *(const float4*)&Ks[j][k4 * 4];
                s[j] = fmaf(q4.x, kk.x, s[j]);
                s[j] = fmaf(q4.y, kk.y, s[j]);
                s[j] = fmaf(q4.z, kk.z, s[j]);
                s[j] = fmaf(q4.w, kk.w, s[j]);
            }
        }

        float tmax = -1e30f;
#pragma unroll
        for (int j = 0; j < FBN; j++) {
            s[j] *= scale;
            tmax = fmaxf(tmax, s[j]);
        }
        const float mnew = fmaxf(m, tmax);
        const float corr = __expf(m - mnew);
        float psum = 0.f;
#pragma unroll
        for (int j = 0; j < FBN; j++) {
            s[j] = __expf(s[j] - mnew);
            psum += s[j];
        }
        l = l * corr + psum;
        m = mnew;

#pragma unroll
        for (int d = 0; d < DH_; d++) acc[d] *= corr;

#pragma unroll
        for (int j = 0; j < FBN; j++) {
            const float pj = s[j];
#pragma unroll
            for (int d4 = 0; d4 < DH_ / 4; d4++) {
                const float4 v4 = *(const float4*)&Vs[j][d4 * 4];
                acc[d4 * 4 + 0] = fmaf(pj, v4.x, acc[d4 * 4 + 0]);
                acc[d4 * 4 + 1] = fmaf(pj, v4.y, acc[d4 * 4 + 1]);
                acc[d4 * 4 + 2] = fmaf(pj, v4.z, acc[d4 * 4 + 2]);
                acc[d4 * 4 + 3] = fmaf(pj, v4.w, acc[d4 * 4 + 3]);
            }
        }
    }

    const float inv = 1.f / l;
    const long ob = qbase + (long)tid * D_;
#pragma unroll
    for (int d4 = 0; d4 < DH_ / 4; d4++) {
        float4 o;
        o.x = acc[d4 * 4 + 0] * inv;
        o.y = acc[d4 * 4 + 1] * inv;
        o.z = acc[d4 * 4 + 2] * inv;
        o.w = acc[d4 * 4 + 3] * inv;
        *(float4*)&O[ob + d4 * 4] = o;
    }
}

// ===========================================================================
extern "C" void kernel_launch(void* const* d_in, const int* in_sizes, int n_in,
                              void* d_out, int out_size)
{
    const float* q  = (const float*)d_in[0];
    const float* kv = (const float*)d_in[1];
    const float* Wq = (const float*)d_in[2];
    const float* bq = (const float*)d_in[3];
    const float* Wk = (const float*)d_in[4];
    const float* bk = (const float*)d_in[5];
    const float* Wv = (const float*)d_in[6];
    const float* bv = (const float*)d_in[7];
    const float* Wo = (const float*)d_in[8];
    const float* bo = (const float*)d_in[9];
    float* out = (float*)d_out;

    float *Qp, *Kp, *Vp, *Op;
    cudaGetSymbolAddress((void**)&Qp, g_Qp);
    cudaGetSymbolAddress((void**)&Kp, g_Kp);
    cudaGetSymbolAddress((void**)&Vp, g_Vp);
    cudaGetSymbolAddress((void**)&Op, g_Op);

    static int smem_set = 0;
    if (!smem_set) {
        cudaFuncSetAttribute(gemm_mma, cudaFuncAttributeMaxDynamicSharedMemorySize, SM_TOTAL);
        smem_set = 1;
    }

    dim3 ggrid(GN / 128, GM / 128);  // (8, 32)

    gemm_mma<<<ggrid, 256, SM_TOTAL>>>(q,  Wq, bq, Qp);
    gemm_mma<<<ggrid, 256, SM_TOTAL>>>(kv, Wk, bk, Kp);
    gemm_mma<<<ggrid, 256, SM_TOTAL>>>(kv, Wv, bv, Vp);

    flash_kernel<<<dim3(NQ_ / FBM, H_, B_), 64>>>(Qp, Kp, Vp, Op);

    gemm_mma<<<ggrid, 256, SM_TOTAL>>>(Op, Wo, bo, out);
}

// round 6
// speedup vs baseline: 3.2626x; 2.8340x over previous
#include <cuda_runtime.h>
#include <cuda_bf16.h>
#include <math.h>
#include <stdint.h>

#define B_   2
#define NQ_  2048
#define NKV_ 2048
#define D_   1024
#define H_   16
#define DH_  64

// Scratch (allocation-free): split-precision projected tensors + attn out
__device__ __nv_bfloat16 g_Qhi[B_ * NQ_ * D_];
__device__ __nv_bfloat16 g_Qlo[B_ * NQ_ * D_];
__device__ __nv_bfloat16 g_Khi[B_ * NKV_ * D_];
__device__ __nv_bfloat16 g_Klo[B_ * NKV_ * D_];
__device__ __nv_bfloat16 g_Vhi[B_ * NKV_ * D_];
__device__ __nv_bfloat16 g_Vlo[B_ * NKV_ * D_];
__device__ float g_Op[B_ * NQ_ * D_];

__device__ __forceinline__ uint32_t smem_u32(const void* p) {
    uint32_t a;
    asm("{ .reg .u64 t; cvta.to.shared.u64 t, %1; cvt.u32.u64 %0, t; }"
        : "=r"(a) : "l"(p));
    return a;
}

__device__ __forceinline__ void mma_bf16(float* d, const uint32_t* a,
                                         uint32_t b0, uint32_t b1) {
    asm volatile(
        "mma.sync.aligned.m16n8k16.row.col.f32.bf16.bf16.f32 "
        "{%0,%1,%2,%3}, {%4,%5,%6,%7}, {%8,%9}, {%0,%1,%2,%3};"
        : "+f"(d[0]), "+f"(d[1]), "+f"(d[2]), "+f"(d[3])
        : "r"(a[0]), "r"(a[1]), "r"(a[2]), "r"(a[3]), "r"(b0), "r"(b1));
}

__device__ __forceinline__ void ldmx4(uint32_t* r, uint32_t addr) {
    asm volatile(
        "ldmatrix.sync.aligned.m8n8.x4.shared.b16 {%0,%1,%2,%3}, [%4];"
        : "=r"(r[0]), "=r"(r[1]), "=r"(r[2]), "=r"(r[3]) : "r"(addr));
}

__device__ __forceinline__ void ldmx4t(uint32_t* r, uint32_t addr) {
    asm volatile(
        "ldmatrix.sync.aligned.m8n8.x4.trans.shared.b16 {%0,%1,%2,%3}, [%4];"
        : "=r"(r[0]), "=r"(r[1]), "=r"(r[2]), "=r"(r[3]) : "r"(addr));
}

__device__ __forceinline__ uint32_t pack_bf16x2(float lo, float hi) {
    uint32_t r;
    asm("cvt.rn.bf16x2.f32 %0, %1, %2;" : "=r"(r) : "f"(hi), "f"(lo));
    return r;
}

// ===========================================================================
// HMMA GEMM core (validated in R5): C = A[M,K] @ W[N,K]^T + bias
// CTA 128x128, K-chunk 64, 256 thr (4x2 warps, warp tile 32x64), bf16x3.
// OUTMODE 0: fp32 C.  OUTMODE 1: bf16 hi/lo pair C, scaled.
// ===========================================================================
#define GM 4096
#define GN 1024
#define GK 1024

#define PITCH_B  144
#define TILE_B   (128 * PITCH_B)
#define SM_STAGE_A 0
#define SM_STAGE_W 32768
#define SM_AHI   65536
#define SM_ALO   (SM_AHI + TILE_B)
#define SM_WHI   (SM_AHI + 2 * TILE_B)
#define SM_WLO   (SM_AHI + 3 * TILE_B)
#define SM_TOTAL (SM_AHI + 4 * TILE_B)   // 139264

template <int OUTMODE>
__global__ __launch_bounds__(256) void gemm_mma(
    const float* __restrict__ A, const float* __restrict__ W,
    const float* __restrict__ bias, float* __restrict__ C,
    __nv_bfloat16* __restrict__ Chi, __nv_bfloat16* __restrict__ Clo,
    float scale)
{
    extern __shared__ char smem[];
    const uint32_t sb = smem_u32(smem);
    const int tid  = threadIdx.x;
    const int wid  = tid >> 5;
    const int lane = tid & 31;
    const int bm = blockIdx.y * 128;
    const int bn = blockIdx.x * 128;
    const int warp_m = wid >> 1;
    const int warp_n = wid & 1;

    float acc[2][8][4];
#pragma unroll
    for (int i = 0; i < 2; i++)
#pragma unroll
        for (int j = 0; j < 8; j++)
#pragma unroll
            for (int k = 0; k < 4; k++) acc[i][j][k] = 0.f;

    auto issue_chunk = [&](int chunk) {
        const int kc = chunk * 64;
#pragma unroll
        for (int it = 0; it < 8; it++) {
            const int idx = it * 256 + tid;
            const int r  = idx >> 4;
            const int c4 = idx & 15;
            const uint32_t da = sb + SM_STAGE_A + (uint32_t)((r * 64 + c4 * 4) * 4);
            const float* sa = A + (long)(bm + r) * GK + kc + c4 * 4;
            asm volatile("cp.async.cg.shared.global [%0], [%1], 16;" :: "r"(da), "l"(sa));
            const uint32_t dw = sb + SM_STAGE_W + (uint32_t)((r * 64 + c4 * 4) * 4);
            const float* sw = W + (long)(bn + r) * GK + kc + c4 * 4;
            asm volatile("cp.async.cg.shared.global [%0], [%1], 16;" :: "r"(dw), "l"(sw));
        }
        asm volatile("cp.async.commit_group;" ::: "memory");
    };

    issue_chunk(0);

    for (int chunk = 0; chunk < GK / 64; chunk++) {
        asm volatile("cp.async.wait_group 0;" ::: "memory");
        __syncthreads();

#pragma unroll
        for (int it = 0; it < 8; it++) {
            const int idx = it * 256 + tid;
            const int r  = idx >> 4;
            const int c4 = idx & 15;
            const float4 va = *(const float4*)(smem + SM_STAGE_A + (r * 64 + c4 * 4) * 4);
            const float4 vw = *(const float4*)(smem + SM_STAGE_W + (r * 64 + c4 * 4) * 4);
            const uint32_t toff = (uint32_t)(r * PITCH_B + c4 * 8);
            {
                __nv_bfloat16 h0 = __float2bfloat16(va.x), h1 = __float2bfloat16(va.y);
                __nv_bfloat16 h2 = __float2bfloat16(va.z), h3 = __float2bfloat16(va.w);
                __nv_bfloat16 l0 = __float2bfloat16(va.x - __bfloat162float(h0));
                __nv_bfloat16 l1 = __float2bfloat16(va.y - __bfloat162float(h1));
                __nv_bfloat16 l2 = __float2bfloat16(va.z - __bfloat162float(h2));
                __nv_bfloat16 l3 = __float2bfloat16(va.w - __bfloat162float(h3));
                __nv_bfloat162 hp0, hp1, lp0, lp1;
                hp0.x = h0; hp0.y = h1; hp1.x = h2; hp1.y = h3;
                lp0.x = l0; lp0.y = l1; lp1.x = l2; lp1.y = l3;
                uint2 hv, lv;
                hv.x = *(uint32_t*)&hp0; hv.y = *(uint32_t*)&hp1;
                lv.x = *(uint32_t*)&lp0; lv.y = *(uint32_t*)&lp1;
                *(uint2*)(smem + SM_AHI + toff) = hv;
                *(uint2*)(smem + SM_ALO + toff) = lv;
            }
            {
                __nv_bfloat16 h0 = __float2bfloat16(vw.x), h1 = __float2bfloat16(vw.y);
                __nv_bfloat16 h2 = __float2bfloat16(vw.z), h3 = __float2bfloat16(vw.w);
                __nv_bfloat16 l0 = __float2bfloat16(vw.x - __bfloat162float(h0));
                __nv_bfloat16 l1 = __float2bfloat16(vw.y - __bfloat162float(h1));
                __nv_bfloat16 l2 = __float2bfloat16(vw.z - __bfloat162float(h2));
                __nv_bfloat16 l3 = __float2bfloat16(vw.w - __bfloat162float(h3));
                __nv_bfloat162 hp0, hp1, lp0, lp1;
                hp0.x = h0; hp0.y = h1; hp1.x = h2; hp1.y = h3;
                lp0.x = l0; lp0.y = l1; lp1.x = l2; lp1.y = l3;
                uint2 hv, lv;
                hv.x = *(uint32_t*)&hp0; hv.y = *(uint32_t*)&hp1;
                lv.x = *(uint32_t*)&lp0; lv.y = *(uint32_t*)&lp1;
                *(uint2*)(smem + SM_WHI + toff) = hv;
                *(uint2*)(smem + SM_WLO + toff) = lv;
            }
        }
        __syncthreads();

        if (chunk + 1 < GK / 64) issue_chunk(chunk + 1);

#pragma unroll
        for (int ks = 0; ks < 4; ks++) {
            uint32_t ah[2][4], al[2][4];
#pragma unroll
            for (int mt = 0; mt < 2; mt++) {
                const uint32_t ra = (uint32_t)((warp_m * 32 + mt * 16 + (lane & 15)) * PITCH_B
                                  + ks * 32 + (lane >> 4) * 16);
                ldmx4(ah[mt], sb + SM_AHI + ra);
                ldmx4(al[mt], sb + SM_ALO + ra);
            }
            uint32_t bh[4][4], bl[4][4];
#pragma unroll
            for (int nt2 = 0; nt2 < 4; nt2++) {
                const uint32_t rb = (uint32_t)((warp_n * 64 + nt2 * 16 + (lane & 15)) * PITCH_B
                                  + ks * 32 + (lane >> 4) * 16);
                ldmx4(bh[nt2], sb + SM_WHI + rb);
                ldmx4(bl[nt2], sb + SM_WLO + rb);
            }
#pragma unroll
            for (int mt = 0; mt < 2; mt++) {
#pragma unroll
                for (int nt = 0; nt < 8; nt++) {
                    const int g = nt >> 1, o = nt & 1;
                    mma_bf16(acc[mt][nt], ah[mt], bh[g][o], bh[g][o + 2]);
                    mma_bf16(acc[mt][nt], ah[mt], bl[g][o], bl[g][o + 2]);
                    mma_bf16(acc[mt][nt], al[mt], bh[g][o], bh[g][o + 2]);
                }
            }
        }
        __syncthreads();
    }

    const int rq = lane >> 2;
    const int cq = (lane & 3) * 2;
#pragma unroll
    for (int mt = 0; mt < 2; mt++) {
        const int r0 = bm + warp_m * 32 + mt * 16 + rq;
#pragma unroll
        for (int nt = 0; nt < 8; nt++) {
            const int c = bn + warp_n * 64 + nt * 8 + cq;
            const float2 bv = *(const float2*)&bias[c];
            if (OUTMODE == 0) {
                float2 o0, o1;
                o0.x = acc[mt][nt][0] + bv.x;
                o0.y = acc[mt][nt][1] + bv.y;
                o1.x = acc[mt][nt][2] + bv.x;
                o1.y = acc[mt][nt][3] + bv.y;
                *(float2*)&C[(long)r0 * GN + c] = o0;
                *(float2*)&C[(long)(r0 + 8) * GN + c] = o1;
            } else {
                const float v0 = (acc[mt][nt][0] + bv.x) * scale;
                const float v1 = (acc[mt][nt][1] + bv.y) * scale;
                const float v2 = (acc[mt][nt][2] + bv.x) * scale;
                const float v3 = (acc[mt][nt][3] + bv.y) * scale;
                __nv_bfloat16 h0 = __float2bfloat16(v0), h1 = __float2bfloat16(v1);
                __nv_bfloat16 h2 = __float2bfloat16(v2), h3 = __float2bfloat16(v3);
                __nv_bfloat16 e0 = __float2bfloat16(v0 - __bfloat162float(h0));
                __nv_bfloat16 e1 = __float2bfloat16(v1 - __bfloat162float(h1));
                __nv_bfloat16 e2 = __float2bfloat16(v2 - __bfloat162float(h2));
                __nv_bfloat16 e3 = __float2bfloat16(v3 - __bfloat162float(h3));
                __nv_bfloat162 hp01, hp23, lp01, lp23;
                hp01.x = h0; hp01.y = h1; hp23.x = h2; hp23.y = h3;
                lp01.x = e0; lp01.y = e1; lp23.x = e2; lp23.y = e3;
                *(uint32_t*)&Chi[(long)r0 * GN + c]       = *(uint32_t*)&hp01;
                *(uint32_t*)&Chi[(long)(r0 + 8) * GN + c] = *(uint32_t*)&hp23;
                *(uint32_t*)&Clo[(long)r0 * GN + c]       = *(uint32_t*)&lp01;
                *(uint32_t*)&Clo[(long)(r0 + 8) * GN + c] = *(uint32_t*)&lp23;
            }
        }
    }
}

// ===========================================================================
// HMMA flash attention. CTA: 64 q-rows x one (b,h); 4 warps (16 rows each).
// KV tiles of 64, double-buffered cp.async. All operands pre-split bf16
// hi/lo by the projection GEMMs (Q pre-scaled by 1/8).
// ===========================================================================
#define FPITCH 144
#define FQT    (64 * FPITCH)          // 9216 bytes per 64x64 bf16 tile
#define FSM_QHI 0
#define FSM_QLO FQT
#define FSM_KV  (2 * FQT)             // 18432
#define FSTAGE  (4 * FQT)             // Khi,Klo,Vhi,Vlo
#define FSM_TOTAL (FSM_KV + 2 * FSTAGE)  // 92160

__global__ __launch_bounds__(128) void flash_mma(
    const __nv_bfloat16* __restrict__ Qhi, const __nv_bfloat16* __restrict__ Qlo,
    const __nv_bfloat16* __restrict__ Khi, const __nv_bfloat16* __restrict__ Klo,
    const __nv_bfloat16* __restrict__ Vhi, const __nv_bfloat16* __restrict__ Vlo,
    float* __restrict__ O)
{
    extern __shared__ char smem[];
    const uint32_t sb = smem_u32(smem);
    const int tid  = threadIdx.x;
    const int wid  = tid >> 5;
    const int lane = tid & 31;
    const int qt = blockIdx.x, h = blockIdx.y, b = blockIdx.z;

    const long qrow0 = (long)b * NQ_ + qt * 64;
    const long krow0 = (long)b * NKV_;
    const int  col0  = h * DH_;

    // ---- prologue: Q tiles + KV stage 0 ----
#pragma unroll
    for (int it = 0; it < 4; it++) {
        const int idx = it * 128 + tid;
        const int r = idx >> 3, c = idx & 7;
        const uint32_t doff = (uint32_t)(r * FPITCH + c * 16);
        const long goff = (qrow0 + r) * D_ + col0 + c * 8;
        asm volatile("cp.async.cg.shared.global [%0], [%1], 16;"
                     :: "r"(sb + FSM_QHI + doff), "l"(Qhi + goff));
        asm volatile("cp.async.cg.shared.global [%0], [%1], 16;"
                     :: "r"(sb + FSM_QLO + doff), "l"(Qlo + goff));
    }
    asm volatile("cp.async.commit_group;" ::: "memory");

    auto issueKV = [&](int kt) {
        const uint32_t base = sb + FSM_KV + (uint32_t)((kt & 1) * FSTAGE);
#pragma unroll
        for (int it = 0; it < 4; it++) {
            const int idx = it * 128 + tid;
            const int r = idx >> 3, c = idx & 7;
            const uint32_t doff = (uint32_t)(r * FPITCH + c * 16);
            const long goff = (krow0 + kt * 64 + r) * D_ + col0 + c * 8;
            asm volatile("cp.async.cg.shared.global [%0], [%1], 16;"
                         :: "r"(base + doff), "l"(Khi + goff));
            asm volatile("cp.async.cg.shared.global [%0], [%1], 16;"
                         :: "r"(base + FQT + doff), "l"(Klo + goff));
            asm volatile("cp.async.cg.shared.global [%0], [%1], 16;"
                         :: "r"(base + 2 * FQT + doff), "l"(Vhi + goff));
            asm volatile("cp.async.cg.shared.global [%0], [%1], 16;"
                         :: "r"(base + 3 * FQT + doff), "l"(Vlo + goff));
        }
        asm volatile("cp.async.commit_group;" ::: "memory");
    };

    issueKV(0);
    asm volatile("cp.async.wait_group 0;" ::: "memory");
    __syncthreads();

    // ---- Q fragments, register-resident for the whole KV loop ----
    const int m0 = wid * 16;
    uint32_t qh[4][4], ql[4][4];
#pragma unroll
    for (int ks = 0; ks < 4; ks++) {
        const uint32_t ra = (uint32_t)((m0 + (lane & 15)) * FPITCH + ks * 32 + (lane >> 4) * 16);
        ldmx4(qh[ks], sb + FSM_QHI + ra);
        ldmx4(ql[ks], sb + FSM_QLO + ra);
    }

    float o[8][4];
#pragma unroll
    for (int i = 0; i < 8; i++)
#pragma unroll
        for (int j = 0; j < 4; j++) o[i][j] = 0.f;
    float mr0 = -1e30f, mr1 = -1e30f, lr0 = 0.f, lr1 = 0.f;

    const int NT = NKV_ / 64;  // 32
    for (int kt = 0; kt < NT; kt++) {
        if (kt + 1 < NT) issueKV(kt + 1);
        if (kt > 0) {
            if (kt + 1 < NT) asm volatile("cp.async.wait_group 1;" ::: "memory");
            else             asm volatile("cp.async.wait_group 0;" ::: "memory");
            __syncthreads();
        }

        const uint32_t kb = sb + FSM_KV + (uint32_t)((kt & 1) * FSTAGE);

        // ---- S = Q K^T (3-term split) ----
        float s[8][4];
#pragma unroll
        for (int i = 0; i < 8; i++)
#pragma unroll
            for (int j = 0; j < 4; j++) s[i][j] = 0.f;

#pragma unroll
        for (int ks = 0; ks < 4; ks++) {
#pragma unroll
            for (int ntp = 0; ntp < 4; ntp++) {
                const uint32_t rb = (uint32_t)((ntp * 16 + (lane & 15)) * FPITCH
                                  + ks * 32 + (lane >> 4) * 16);
                uint32_t bh[4], bl[4];
                ldmx4(bh, kb + rb);
                ldmx4(bl, kb + FQT + rb);
#pragma unroll
                for (int oo = 0; oo < 2; oo++) {
                    float* d = s[ntp * 2 + oo];
                    mma_bf16(d, qh[ks], bh[oo], bh[oo + 2]);
                    mma_bf16(d, qh[ks], bl[oo], bl[oo + 2]);
                    mma_bf16(d, ql[ks], bh[oo], bh[oo + 2]);
                }
            }
        }

        // ---- online softmax (rows r = lane>>2 and r+8, quad-local) ----
        float tm0 = -1e30f, tm1 = -1e30f;
#pragma unroll
        for (int i = 0; i < 8; i++) {
            tm0 = fmaxf(tm0, fmaxf(s[i][0], s[i][1]));
            tm1 = fmaxf(tm1, fmaxf(s[i][2], s[i][3]));
        }
        tm0 = fmaxf(tm0, __shfl_xor_sync(0xffffffffu, tm0, 1));
        tm0 = fmaxf(tm0, __shfl_xor_sync(0xffffffffu, tm0, 2));
        tm1 = fmaxf(tm1, __shfl_xor_sync(0xffffffffu, tm1, 1));
        tm1 = fmaxf(tm1, __shfl_xor_sync(0xffffffffu, tm1, 2));

        const float mn0 = fmaxf(mr0, tm0);
        const float mn1 = fmaxf(mr1, tm1);
        const float cr0 = __expf(mr0 - mn0);
        const float cr1 = __expf(mr1 - mn1);
        mr0 = mn0; mr1 = mn1;

        float ps0 = 0.f, ps1 = 0.f;
#pragma unroll
        for (int i = 0; i < 8; i++) {
            s[i][0] = __expf(s[i][0] - mn0);
            s[i][1] = __expf(s[i][1] - mn0);
            s[i][2] = __expf(s[i][2] - mn1);
            s[i][3] = __expf(s[i][3] - mn1);
            ps0 += s[i][0] + s[i][1];
            ps1 += s[i][2] + s[i][3];
        }
        ps0 += __shfl_xor_sync(0xffffffffu, ps0, 1);
        ps0 += __shfl_xor_sync(0xffffffffu, ps0, 2);
        ps1 += __shfl_xor_sync(0xffffffffu, ps1, 1);
        ps1 += __shfl_xor_sync(0xffffffffu, ps1, 2);
        lr0 = lr0 * cr0 + ps0;
        lr1 = lr1 * cr1 + ps1;

#pragma unroll
        for (int i = 0; i < 8; i++) {
            o[i][0] *= cr0; o[i][1] *= cr0;
            o[i][2] *= cr1; o[i][3] *= cr1;
        }

        // ---- O += P V  (P split hi/lo in registers, V pre-split) ----
#pragma unroll
        for (int ks2 = 0; ks2 < 4; ks2++) {
            const int n0 = 2 * ks2, n1 = 2 * ks2 + 1;
            uint32_t ph[4], pl[4];
            float rv[8];
#pragma unroll
            for (int e = 0; e < 4; e++) {
                const float v0 = s[n0][e], v1 = s[n1][e];
                const __nv_bfloat16 h0 = __float2bfloat16(v0);
                const __nv_bfloat16 h1 = __float2bfloat16(v1);
                rv[e]     = v0 - __bfloat162float(h0);
                rv[e + 4] = v1 - __bfloat162float(h1);
            }
            ph[0] = pack_bf16x2(s[n0][0], s[n0][1]);
            ph[1] = pack_bf16x2(s[n0][2], s[n0][3]);
            ph[2] = pack_bf16x2(s[n1][0], s[n1][1]);
            ph[3] = pack_bf16x2(s[n1][2], s[n1][3]);
            pl[0] = pack_bf16x2(rv[0], rv[1]);
            pl[1] = pack_bf16x2(rv[2], rv[3]);
            pl[2] = pack_bf16x2(rv[4], rv[5]);
            pl[3] = pack_bf16x2(rv[6], rv[7]);

#pragma unroll
            for (int ntp = 0; ntp < 4; ntp++) {
                const uint32_t rv2 = (uint32_t)((ks2 * 16 + (lane & 15)) * FPITCH
                                   + ntp * 32 + (lane >> 4) * 16);
                uint32_t vh[4], vl[4];
                ldmx4t(vh, kb + 2 * FQT + rv2);
                ldmx4t(vl, kb + 3 * FQT + rv2);
#pragma unroll
                for (int o2 = 0; o2 < 2; o2++) {
                    float* d = o[ntp * 2 + o2];
                    mma_bf16(d, ph, vh[o2 * 2], vh[o2 * 2 + 1]);
                    mma_bf16(d, ph, vl[o2 * 2], vl[o2 * 2 + 1]);
                    mma_bf16(d, pl, vh[o2 * 2], vh[o2 * 2 + 1]);
                }
            }
        }
        __syncthreads();
    }

    // ---- finalize: normalize + store fp32 ----
    const float inv0 = 1.f / lr0;
    const float inv1 = 1.f / lr1;
    const int r = lane >> 2;
    const long orow = (qrow0 + m0 + r) * D_ + col0;
#pragma unroll
    for (int nt = 0; nt < 8; nt++) {
        const int c = nt * 8 + (lane & 3) * 2;
        float2 w0, w1;
        w0.x = o[nt][0] * inv0; w0.y = o[nt][1] * inv0;
        w1.x = o[nt][2] * inv1; w1.y = o[nt][3] * inv1;
        *(float2*)&O[orow + c] = w0;
        *(float2*)&O[orow + 8 * D_ + c] = w1;
    }
}

// ===========================================================================
extern "C" void kernel_launch(void* const* d_in, const int* in_sizes, int n_in,
                              void* d_out, int out_size)
{
    const float* q  = (const float*)d_in[0];
    const float* kv = (const float*)d_in[1];
    const float* Wq = (const float*)d_in[2];
    const float* bq = (const float*)d_in[3];
    const float* Wk = (const float*)d_in[4];
    const float* bk = (const float*)d_in[5];
    const float* Wv = (const float*)d_in[6];
    const float* bv = (const float*)d_in[7];
    const float* Wo = (const float*)d_in[8];
    const float* bo = (const float*)d_in[9];
    float* out = (float*)d_out;

    __nv_bfloat16 *Qhi, *Qlo, *Khi, *Klo, *Vhi, *Vlo;
    float *Op;
    cudaGetSymbolAddress((void**)&Qhi, g_Qhi);
    cudaGetSymbolAddress((void**)&Qlo, g_Qlo);
    cudaGetSymbolAddress((void**)&Khi, g_Khi);
    cudaGetSymbolAddress((void**)&Klo, g_Klo);
    cudaGetSymbolAddress((void**)&Vhi, g_Vhi);
    cudaGetSymbolAddress((void**)&Vlo, g_Vlo);
    cudaGetSymbolAddress((void**)&Op,  g_Op);

    cudaFuncSetAttribute(gemm_mma<0>, cudaFuncAttributeMaxDynamicSharedMemorySize, SM_TOTAL);
    cudaFuncSetAttribute(gemm_mma<1>, cudaFuncAttributeMaxDynamicSharedMemorySize, SM_TOTAL);
    cudaFuncSetAttribute(flash_mma,   cudaFuncAttributeMaxDynamicSharedMemorySize, FSM_TOTAL);

    dim3 ggrid(GN / 128, GM / 128);  // (8, 32)

    gemm_mma<1><<<ggrid, 256, SM_TOTAL>>>(q,  Wq, bq, nullptr, Qhi, Qlo, 0.125f);
    gemm_mma<1><<<ggrid, 256, SM_TOTAL>>>(kv, Wk, bk, nullptr, Khi, Klo, 1.0f);
    gemm_mma<1><<<ggrid, 256, SM_TOTAL>>>(kv, Wv, bv, nullptr, Vhi, Vlo, 1.0f);

    flash_mma<<<dim3(NQ_ / 64, H_, B_), 128, FSM_TOTAL>>>(Qhi, Qlo, Khi, Klo, Vhi, Vlo, Op);

    gemm_mma<0><<<ggrid, 256, SM_TOTAL>>>(Op, Wo, bo, out, nullptr, nullptr, 1.0f);
}

// round 10
// speedup vs baseline: 3.5526x; 1.0889x over previous
#include <cuda_runtime.h>
#include <cuda_bf16.h>
#include <math.h>
#include <stdint.h>

#define B_   2
#define NQ_  2048
#define NKV_ 2048
#define D_   1024
#define H_   16
#define DH_  64

// ---- Scratch (allocation-free) ----
// Pre-split GEMM inputs
__device__ __nv_bfloat16 g_qhi[B_ * NQ_ * D_];
__device__ __nv_bfloat16 g_qlo[B_ * NQ_ * D_];
__device__ __nv_bfloat16 g_kvhi[B_ * NKV_ * D_];
__device__ __nv_bfloat16 g_kvlo[B_ * NKV_ * D_];
__device__ __nv_bfloat16 g_Wqhi[D_ * D_], g_Wqlo[D_ * D_];
__device__ __nv_bfloat16 g_Wkhi[D_ * D_], g_Wklo[D_ * D_];
__device__ __nv_bfloat16 g_Wvhi[D_ * D_], g_Wvlo[D_ * D_];
__device__ __nv_bfloat16 g_Wohi[D_ * D_], g_Wolo[D_ * D_];
// Projection outputs (split)
__device__ __nv_bfloat16 g_Qhi[B_ * NQ_ * D_], g_Qlo[B_ * NQ_ * D_];
__device__ __nv_bfloat16 g_Khi[B_ * NKV_ * D_], g_Klo[B_ * NKV_ * D_];
__device__ __nv_bfloat16 g_Vhi[B_ * NKV_ * D_], g_Vlo[B_ * NKV_ * D_];
// Flash output (split)
__device__ __nv_bfloat16 g_Ophi[B_ * NQ_ * D_], g_Oplo[B_ * NQ_ * D_];

__device__ __forceinline__ uint32_t smem_u32(const void* p) {
    uint32_t a;
    asm("{ .reg .u64 t; cvta.to.shared.u64 t, %1; cvt.u32.u64 %0, t; }"
        : "=r"(a) : "l"(p));
    return a;
}

__device__ __forceinline__ void mma_bf16(float* d, const uint32_t* a,
                                         uint32_t b0, uint32_t b1) {
    asm volatile(
        "mma.sync.aligned.m16n8k16.row.col.f32.bf16.bf16.f32 "
        "{%0,%1,%2,%3}, {%4,%5,%6,%7}, {%8,%9}, {%0,%1,%2,%3};"
        : "+f"(d[0]), "+f"(d[1]), "+f"(d[2]), "+f"(d[3])
        : "r"(a[0]), "r"(a[1]), "r"(a[2]), "r"(a[3]), "r"(b0), "r"(b1));
}

__device__ __forceinline__ void ldmx4(uint32_t* r, uint32_t addr) {
    asm volatile(
        "ldmatrix.sync.aligned.m8n8.x4.shared.b16 {%0,%1,%2,%3}, [%4];"
        : "=r"(r[0]), "=r"(r[1]), "=r"(r[2]), "=r"(r[3]) : "r"(addr));
}

__device__ __forceinline__ void ldmx4t(uint32_t* r, uint32_t addr) {
    asm volatile(
        "ldmatrix.sync.aligned.m8n8.x4.trans.shared.b16 {%0,%1,%2,%3}, [%4];"
        : "=r"(r[0]), "=r"(r[1]), "=r"(r[2]), "=r"(r[3]) : "r"(addr));
}

__device__ __forceinline__ uint32_t pack_bf16x2(float lo, float hi) {
    uint32_t r;
    asm("cvt.rn.bf16x2.f32 %0, %1, %2;" : "=r"(r) : "f"(hi), "f"(lo));
    return r;
}

#define CP16(dst, src) \
    asm volatile("cp.async.cg.shared.global [%0], [%1], 16;" :: "r"(dst), "l"(src))
#define CP_COMMIT() asm volatile("cp.async.commit_group;" ::: "memory")
#define CP_WAIT0()  asm volatile("cp.async.wait_group 0;" ::: "memory")

// ===========================================================================
// split kernel: x fp32 -> hi/lo bf16 (hi = bf16(x), lo = bf16(x - hi))
// ===========================================================================
__global__ __launch_bounds__(256) void split_kernel(
    const float* __restrict__ x, __nv_bfloat16* __restrict__ hi,
    __nv_bfloat16* __restrict__ lo)
{
    const int i = (blockIdx.x * 256 + threadIdx.x) * 4;
    const float4 v = *(const float4*)(x + i);
    __nv_bfloat16 h0 = __float2bfloat16(v.x), h1 = __float2bfloat16(v.y);
    __nv_bfloat16 h2 = __float2bfloat16(v.z), h3 = __float2bfloat16(v.w);
    __nv_bfloat16 l0 = __float2bfloat16(v.x - __bfloat162float(h0));
    __nv_bfloat16 l1 = __float2bfloat16(v.y - __bfloat162float(h1));
    __nv_bfloat16 l2 = __float2bfloat16(v.z - __bfloat162float(h2));
    __nv_bfloat16 l3 = __float2bfloat16(v.w - __bfloat162float(h3));
    __nv_bfloat162 hp0, hp1, lp0, lp1;
    hp0.x = h0; hp0.y = h1; hp1.x = h2; hp1.y = h3;
    lp0.x = l0; lp0.y = l1; lp1.x = l2; lp1.y = l3;
    uint2 hv, lv;
    hv.x = *(uint32_t*)&hp0; hv.y = *(uint32_t*)&hp1;
    lv.x = *(uint32_t*)&lp0; lv.y = *(uint32_t*)&lp1;
    *(uint2*)(hi + i) = hv;
    *(uint2*)(lo + i) = lv;
}

// ===========================================================================
// Pre-split HMMA GEMM: C = A[M,K] @ W[N,K]^T + bias  (bf16x3, all operands
// pre-split in global). CTA 128x128, K-chunk 64, double-buffered cp.async,
// 256 thr (4x2 warps, warp tile 32x64). No convert pass.
// OUTMODE 0: fp32 C.  OUTMODE 1: bf16 hi/lo C, scaled.
// ===========================================================================
#define GM 4096
#define GN 1024
#define GK 1024
#define PITCH_B 144
#define GT  (128 * PITCH_B)      // 18432 per tile
#define GST (4 * GT)             // 73728 per stage (Ahi,Alo,Whi,Wlo)
#define SM_TOTAL (2 * GST)       // 147456

template <int OUTMODE>
__global__ __launch_bounds__(256) void gemm_ps(
    const __nv_bfloat16* __restrict__ Ahi, const __nv_bfloat16* __restrict__ Alo,
    const __nv_bfloat16* __restrict__ Whi, const __nv_bfloat16* __restrict__ Wlo,
    const float* __restrict__ bias, float* __restrict__ C,
    __nv_bfloat16* __restrict__ Chi, __nv_bfloat16* __restrict__ Clo,
    float scale)
{
    extern __shared__ char smem[];
    const uint32_t sb = smem_u32(smem);
    const int tid  = threadIdx.x;
    const int wid  = tid >> 5;
    const int lane = tid & 31;
    const int bm = blockIdx.y * 128;
    const int bn = blockIdx.x * 128;
    const int warp_m = wid >> 1;
    const int warp_n = wid & 1;

    float acc[2][8][4];
#pragma unroll
    for (int i = 0; i < 2; i++)
#pragma unroll
        for (int j = 0; j < 8; j++)
#pragma unroll
            for (int k = 0; k < 4; k++) acc[i][j][k] = 0.f;

    auto issue_chunk = [&](int chunk) {
        const uint32_t base = sb + (uint32_t)((chunk & 1) * GST);
        const int kc = chunk * 64;
#pragma unroll
        for (int it = 0; it < 16; it++) {
            const int t   = it >> 2;                // tile: Ahi,Alo,Whi,Wlo
            const int sub = (it & 3) * 256 + tid;   // 0..1023
            const int r   = sub >> 3;               // 0..127
            const int c   = sub & 7;                // 16B chunk in row
            const uint32_t dst = base + (uint32_t)(t * GT + r * PITCH_B + c * 16);
            const __nv_bfloat16* src;
            if      (t == 0) src = Ahi + (long)(bm + r) * GK + kc + c * 8;
            else if (t == 1) src = Alo + (long)(bm + r) * GK + kc + c * 8;
            else if (t == 2) src = Whi + (long)(bn + r) * GK + kc + c * 8;
            else             src = Wlo + (long)(bn + r) * GK + kc + c * 8;
            CP16(dst, src);
        }
        CP_COMMIT();
    };

    issue_chunk(0);

    for (int chunk = 0; chunk < GK / 64; chunk++) {
        CP_WAIT0();
        __syncthreads();
        if (chunk + 1 < GK / 64) issue_chunk(chunk + 1);

        const uint32_t base = sb + (uint32_t)((chunk & 1) * GST);
#pragma unroll
        for (int ks = 0; ks < 4; ks++) {
            uint32_t ah[2][4], al[2][4];
#pragma unroll
            for (int mt = 0; mt < 2; mt++) {
                const uint32_t ra = (uint32_t)((warp_m * 32 + mt * 16 + (lane & 15)) * PITCH_B
                                  + ks * 32 + (lane >> 4) * 16);
                ldmx4(ah[mt], base + ra);
                ldmx4(al[mt], base + GT + ra);
            }
            uint32_t bh[4][4], bl[4][4];
#pragma unroll
            for (int nt2 = 0; nt2 < 4; nt2++) {
                const uint32_t rb = (uint32_t)((warp_n * 64 + nt2 * 16 + (lane & 15)) * PITCH_B
                                  + ks * 32 + (lane >> 4) * 16);
                ldmx4(bh[nt2], base + 2 * GT + rb);
                ldmx4(bl[nt2], base + 3 * GT + rb);
            }
#pragma unroll
            for (int mt = 0; mt < 2; mt++) {
#pragma unroll
                for (int nt = 0; nt < 8; nt++) {
                    const int g = nt >> 1, o = nt & 1;
                    mma_bf16(acc[mt][nt], ah[mt], bh[g][o], bh[g][o + 2]);
                    mma_bf16(acc[mt][nt], ah[mt], bl[g][o], bl[g][o + 2]);
                    mma_bf16(acc[mt][nt], al[mt], bh[g][o], bh[g][o + 2]);
                }
            }
        }
    }

    const int rq = lane >> 2;
    const int cq = (lane & 3) * 2;
#pragma unroll
    for (int mt = 0; mt < 2; mt++) {
        const int r0 = bm + warp_m * 32 + mt * 16 + rq;
#pragma unroll
        for (int nt = 0; nt < 8; nt++) {
            const int c = bn + warp_n * 64 + nt * 8 + cq;
            const float2 bv = *(const float2*)&bias[c];
            if (OUTMODE == 0) {
                float2 o0, o1;
                o0.x = acc[mt][nt][0] + bv.x;
                o0.y = acc[mt][nt][1] + bv.y;
                o1.x = acc[mt][nt][2] + bv.x;
                o1.y = acc[mt][nt][3] + bv.y;
                *(float2*)&C[(long)r0 * GN + c] = o0;
                *(float2*)&C[(long)(r0 + 8) * GN + c] = o1;
            } else {
                const float v0 = (acc[mt][nt][0] + bv.x) * scale;
                const float v1 = (acc[mt][nt][1] + bv.y) * scale;
                const float v2 = (acc[mt][nt][2] + bv.x) * scale;
                const float v3 = (acc[mt][nt][3] + bv.y) * scale;
                const float h0 = __bfloat162float(__float2bfloat16(v0));
                const float h1 = __bfloat162float(__float2bfloat16(v1));
                const float h2 = __bfloat162float(__float2bfloat16(v2));
                const float h3 = __bfloat162float(__float2bfloat16(v3));
                *(uint32_t*)&Chi[(long)r0 * GN + c]       = pack_bf16x2(v0, v1);
                *(uint32_t*)&Chi[(long)(r0 + 8) * GN + c] = pack_bf16x2(v2, v3);
                *(uint32_t*)&Clo[(long)r0 * GN + c]       = pack_bf16x2(v0 - h0, v1 - h1);
                *(uint32_t*)&Clo[(long)(r0 + 8) * GN + c] = pack_bf16x2(v2 - h2, v3 - h3);
            }
        }
    }
}

// ===========================================================================
// HMMA flash attention. CTA: 64 q-rows x one (b,h); 4 warps.
// KV tiles of 64, double-buffered. Q smem overlaid on KV stage 1 (dead after
// prologue fragment loads) -> 72KB smem -> 3 CTAs/SM.
// Outputs split bf16 hi/lo for the O-projection GEMM.
// ===========================================================================
#define FPITCH 144
#define FT  (64 * FPITCH)          // 9216 per 64x64 tile
#define FST (4 * FT)               // 36864 per KV stage
#define FSM_QHI (FST)              // Q tiles live inside stage 1
#define FSM_QLO (FST + FT)
#define FSM_TOTAL (2 * FST)        // 73728

__global__ __launch_bounds__(128) void flash_mma(
    const __nv_bfloat16* __restrict__ Qhi, const __nv_bfloat16* __restrict__ Qlo,
    const __nv_bfloat16* __restrict__ Khi, const __nv_bfloat16* __restrict__ Klo,
    const __nv_bfloat16* __restrict__ Vhi, const __nv_bfloat16* __restrict__ Vlo,
    __nv_bfloat16* __restrict__ Ophi, __nv_bfloat16* __restrict__ Oplo)
{
    extern __shared__ char smem[];
    const uint32_t sb = smem_u32(smem);
    const int tid  = threadIdx.x;
    const int wid  = tid >> 5;
    const int lane = tid & 31;
    const int qt = blockIdx.x, h = blockIdx.y, b = blockIdx.z;

    const long qrow0 = (long)b * NQ_ + qt * 64;
    const long krow0 = (long)b * NKV_;
    const int  col0  = h * DH_;

    auto issueKV = [&](int kt) {
        const uint32_t base = sb + (uint32_t)((kt & 1) * FST);
#pragma unroll
        for (int it = 0; it < 4; it++) {
            const int idx = it * 128 + tid;
            const int r = idx >> 3, c = idx & 7;
            const uint32_t doff = (uint32_t)(r * FPITCH + c * 16);
            const long goff = (krow0 + kt * 64 + r) * D_ + col0 + c * 8;
            CP16(base + doff,          Khi + goff);
            CP16(base + FT + doff,     Klo + goff);
            CP16(base + 2 * FT + doff, Vhi + goff);
            CP16(base + 3 * FT + doff, Vlo + goff);
        }
        CP_COMMIT();
    };

    // ---- prologue: Q tiles (into stage-1 area) + KV stage 0 ----
#pragma unroll
    for (int it = 0; it < 4; it++) {
        const int idx = it * 128 + tid;
        const int r = idx >> 3, c = idx & 7;
        const uint32_t doff = (uint32_t)(r * FPITCH + c * 16);
        const long goff = (qrow0 + r) * D_ + col0 + c * 8;
        CP16(sb + FSM_QHI + doff, Qhi + goff);
        CP16(sb + FSM_QLO + doff, Qlo + goff);
    }
    issueKV(0);
    CP_WAIT0();
    __syncthreads();

    // ---- Q fragments, register-resident ----
    const int m0 = wid * 16;
    uint32_t qh[4][4], ql[4][4];
#pragma unroll
    for (int ks = 0; ks < 4; ks++) {
        const uint32_t ra = (uint32_t)((m0 + (lane & 15)) * FPITCH + ks * 32 + (lane >> 4) * 16);
        ldmx4(qh[ks], sb + FSM_QHI + ra);
        ldmx4(ql[ks], sb + FSM_QLO + ra);
    }

    float o[8][4];
#pragma unroll
    for (int i = 0; i < 8; i++)
#pragma unroll
        for (int j = 0; j < 4; j++) o[i][j] = 0.f;
    float mr0 = -1e30f, mr1 = -1e30f, lr0 = 0.f, lr1 = 0.f;

    const int NT = NKV_ / 64;  // 32
    for (int kt = 0; kt < NT; kt++) {
        CP_WAIT0();
        __syncthreads();                 // stage ready; Q frags loaded (kt=0)
        if (kt + 1 < NT) issueKV(kt + 1);

        const uint32_t kb = sb + (uint32_t)((kt & 1) * FST);

        // ---- S = Q K^T ----
        float s[8][4];
#pragma unroll
        for (int i = 0; i < 8; i++)
#pragma unroll
            for (int j = 0; j < 4; j++) s[i][j] = 0.f;

#pragma unroll
        for (int ks = 0; ks < 4; ks++) {
#pragma unroll
            for (int ntp = 0; ntp < 4; ntp++) {
                const uint32_t rb = (uint32_t)((ntp * 16 + (lane & 15)) * FPITCH
                                  + ks * 32 + (lane >> 4) * 16);
                uint32_t bh[4], bl[4];
                ldmx4(bh, kb + rb);
                ldmx4(bl, kb + FT + rb);
#pragma unroll
                for (int oo = 0; oo < 2; oo++) {
                    float* d = s[ntp * 2 + oo];
                    mma_bf16(d, qh[ks], bh[oo], bh[oo + 2]);
                    mma_bf16(d, qh[ks], bl[oo], bl[oo + 2]);
                    mma_bf16(d, ql[ks], bh[oo], bh[oo + 2]);
                }
            }
        }

        // ---- online softmax ----
        float tm0 = -1e30f, tm1 = -1e30f;
#pragma unroll
        for (int i = 0; i < 8; i++) {
            tm0 = fmaxf(tm0, fmaxf(s[i][0], s[i][1]));
            tm1 = fmaxf(tm1, fmaxf(s[i][2], s[i][3]));
        }
        tm0 = fmaxf(tm0, __shfl_xor_sync(0xffffffffu, tm0, 1));
        tm0 = fmaxf(tm0, __shfl_xor_sync(0xffffffffu, tm0, 2));
        tm1 = fmaxf(tm1, __shfl_xor_sync(0xffffffffu, tm1, 1));
        tm1 = fmaxf(tm1, __shfl_xor_sync(0xffffffffu, tm1, 2));

        const float mn0 = fmaxf(mr0, tm0);
        const float mn1 = fmaxf(mr1, tm1);
        const float cr0 = __expf(mr0 - mn0);
        const float cr1 = __expf(mr1 - mn1);
        mr0 = mn0; mr1 = mn1;

        float ps0 = 0.f, ps1 = 0.f;
#pragma unroll
        for (int i = 0; i < 8; i++) {
            s[i][0] = __expf(s[i][0] - mn0);
            s[i][1] = __expf(s[i][1] - mn0);
            s[i][2] = __expf(s[i][2] - mn1);
            s[i][3] = __expf(s[i][3] - mn1);
            ps0 += s[i][0] + s[i][1];
            ps1 += s[i][2] + s[i][3];
        }
        ps0 += __shfl_xor_sync(0xffffffffu, ps0, 1);
        ps0 += __shfl_xor_sync(0xffffffffu, ps0, 2);
        ps1 += __shfl_xor_sync(0xffffffffu, ps1, 1);
        ps1 += __shfl_xor_sync(0xffffffffu, ps1, 2);
        lr0 = lr0 * cr0 + ps0;
        lr1 = lr1 * cr1 + ps1;

#pragma unroll
        for (int i = 0; i < 8; i++) {
            o[i][0] *= cr0; o[i][1] *= cr0;
            o[i][2] *= cr1; o[i][3] *= cr1;
        }

        // ---- O += P V ----
#pragma unroll
        for (int ks2 = 0; ks2 < 4; ks2++) {
            const int n0 = 2 * ks2, n1 = 2 * ks2 + 1;
            uint32_t ph[4], pl[4];
            float rv[8];
#pragma unroll
            for (int e = 0; e < 4; e++) {
                const float v0 = s[n0][e], v1 = s[n1][e];
                rv[e]     = v0 - __bfloat162float(__float2bfloat16(v0));
                rv[e + 4] = v1 - __bfloat162float(__float2bfloat16(v1));
            }
            ph[0] = pack_bf16x2(s[n0][0], s[n0][1]);
            ph[1] = pack_bf16x2(s[n0][2], s[n0][3]);
            ph[2] = pack_bf16x2(s[n1][0], s[n1][1]);
            ph[3] = pack_bf16x2(s[n1][2], s[n1][3]);
            pl[0] = pack_bf16x2(rv[0], rv[1]);
            pl[1] = pack_bf16x2(rv[2], rv[3]);
            pl[2] = pack_bf16x2(rv[4], rv[5]);
            pl[3] = pack_bf16x2(rv[6], rv[7]);

#pragma unroll
            for (int ntp = 0; ntp < 4; ntp++) {
                const uint32_t rv2 = (uint32_t)((ks2 * 16 + (lane & 15)) * FPITCH
                                   + ntp * 32 + (lane >> 4) * 16);
                uint32_t vh[4], vl[4];
                ldmx4t(vh, kb + 2 * FT + rv2);
                ldmx4t(vl, kb + 3 * FT + rv2);
#pragma unroll
                for (int o2 = 0; o2 < 2; o2++) {
                    float* d = o[ntp * 2 + o2];
                    mma_bf16(d, ph, vh[o2 * 2], vh[o2 * 2 + 1]);
                    mma_bf16(d, ph, vl[o2 * 2], vl[o2 * 2 + 1]);
                    mma_bf16(d, pl, vh[o2 * 2], vh[o2 * 2 + 1]);
                }
            }
        }
    }

    // ---- finalize: normalize + split-store bf16 hi/lo ----
    const float inv0 = 1.f / lr0;
    const float inv1 = 1.f / lr1;
    const int r = lane >> 2;
    const long orow = (qrow0 + m0 + r) * D_ + col0;
#pragma unroll
    for (int nt = 0; nt < 8; nt++) {
        const int c = nt * 8 + (lane & 3) * 2;
        const float a0 = o[nt][0] * inv0, a1 = o[nt][1] * inv0;
        const float a2 = o[nt][2] * inv1, a3 = o[nt][3] * inv1;
        const float h0 = __bfloat162float(__float2bfloat16(a0));
        const float h1 = __bfloat162float(__float2bfloat16(a1));
        const float h2 = __bfloat162float(__float2bfloat16(a2));
        const float h3 = __bfloat162float(__float2bfloat16(a3));
        *(uint32_t*)&Ophi[orow + c]           = pack_bf16x2(a0, a1);
        *(uint32_t*)&Ophi[orow + 8 * D_ + c]  = pack_bf16x2(a2, a3);
        *(uint32_t*)&Oplo[orow + c]           = pack_bf16x2(a0 - h0, a1 - h1);
        *(uint32_t*)&Oplo[orow + 8 * D_ + c]  = pack_bf16x2(a2 - h2, a3 - h3);
    }
}

// ===========================================================================
extern "C" void kernel_launch(void* const* d_in, const int* in_sizes, int n_in,
                              void* d_out, int out_size)
{
    const float* q  = (const float*)d_in[0];
    const float* kv = (const float*)d_in[1];
    const float* Wq = (const float*)d_in[2];
    const float* bq = (const float*)d_in[3];
    const float* Wk = (const float*)d_in[4];
    const float* bk = (const float*)d_in[5];
    const float* Wv = (const float*)d_in[6];
    const float* bv = (const float*)d_in[7];
    const float* Wo = (const float*)d_in[8];
    const float* bo = (const float*)d_in[9];
    float* out = (float*)d_out;

    __nv_bfloat16 *qhi, *qlo, *kvhi, *kvlo;
    __nv_bfloat16 *Wqhi, *Wqlo, *Wkhi, *Wklo, *Wvhi, *Wvlo, *Wohi, *Wolo;
    __nv_bfloat16 *Qhi, *Qlo, *Khi, *Klo, *Vhi, *Vlo, *Ophi, *Oplo;
    cudaGetSymbolAddress((void**)&qhi,  g_qhi);
    cudaGetSymbolAddress((void**)&qlo,  g_qlo);
    cudaGetSymbolAddress((void**)&kvhi, g_kvhi);
    cudaGetSymbolAddress((void**)&kvlo, g_kvlo);
    cudaGetSymbolAddress((void**)&Wqhi, g_Wqhi);
    cudaGetSymbolAddress((void**)&Wqlo, g_Wqlo);
    cudaGetSymbolAddress((void**)&Wkhi, g_Wkhi);
    cudaGetSymbolAddress((void**)&Wklo, g_Wklo);
    cudaGetSymbolAddress((void**)&Wvhi, g_Wvhi);
    cudaGetSymbolAddress((void**)&Wvlo, g_Wvlo);
    cudaGetSymbolAddress((void**)&Wohi, g_Wohi);
    cudaGetSymbolAddress((void**)&Wolo, g_Wolo);
    cudaGetSymbolAddress((void**)&Qhi,  g_Qhi);
    cudaGetSymbolAddress((void**)&Qlo,  g_Qlo);
    cudaGetSymbolAddress((void**)&Khi,  g_Khi);
    cudaGetSymbolAddress((void**)&Klo,  g_Klo);
    cudaGetSymbolAddress((void**)&Vhi,  g_Vhi);
    cudaGetSymbolAddress((void**)&Vlo,  g_Vlo);
    cudaGetSymbolAddress((void**)&Ophi, g_Ophi);
    cudaGetSymbolAddress((void**)&Oplo, g_Oplo);

    cudaFuncSetAttribute(gemm_ps<0>, cudaFuncAttributeMaxDynamicSharedMemorySize, SM_TOTAL);
    cudaFuncSetAttribute(gemm_ps<1>, cudaFuncAttributeMaxDynamicSharedMemorySize, SM_TOTAL);
    cudaFuncSetAttribute(flash_mma,  cudaFuncAttributeMaxDynamicSharedMemorySize, FSM_TOTAL);

    // ---- pre-split all GEMM inputs ----
    const int NQK = B_ * NQ_ * D_;     // 4M
    const int NW  = D_ * D_;           // 1M
    split_kernel<<<NQK / 1024, 256>>>(q,  qhi,  qlo);
    split_kernel<<<NQK / 1024, 256>>>(kv, kvhi, kvlo);
    split_kernel<<<NW / 1024, 256>>>(Wq, Wqhi, Wqlo);
    split_kernel<<<NW / 1024, 256>>>(Wk, Wkhi, Wklo);
    split_kernel<<<NW / 1024, 256>>>(Wv, Wvhi, Wvlo);
    split_kernel<<<NW / 1024, 256>>>(Wo, Wohi, Wolo);

    dim3 ggrid(GN / 128, GM / 128);  // (8, 32)

    gemm_ps<1><<<ggrid, 256, SM_TOTAL>>>(qhi,  qlo,  Wqhi, Wqlo, bq, nullptr, Qhi, Qlo, 0.125f);
    gemm_ps<1><<<ggrid, 256, SM_TOTAL>>>(kvhi, kvlo, Wkhi, Wklo, bk, nullptr, Khi, Klo, 1.0f);
    gemm_ps<1><<<ggrid, 256, SM_TOTAL>>>(kvhi, kvlo, Wvhi, Wvlo, bv, nullptr, Vhi, Vlo, 1.0f);

    flash_mma<<<dim3(NQ_ / 64, H_, B_), 128, FSM_TOTAL>>>(Qhi, Qlo, Khi, Klo, Vhi, Vlo, Ophi, Oplo);

    gemm_ps<0><<<ggrid, 256, SM_TOTAL>>>(Ophi, Oplo, Wohi, Wolo, bo, out, nullptr, nullptr, 1.0f);
}

// round 11
// speedup vs baseline: 3.5931x; 1.0114x over previous
#include <cuda_runtime.h>
#include <cuda_bf16.h>
#include <math.h>
#include <stdint.h>

#define B_   2
#define NQ_  2048
#define NKV_ 2048
#define D_   1024
#define H_   16
#define DH_  64

// ---- Scratch (allocation-free) ----
__device__ __nv_bfloat16 g_qhi[B_ * NQ_ * D_];
__device__ __nv_bfloat16 g_qlo[B_ * NQ_ * D_];
__device__ __nv_bfloat16 g_kvhi[B_ * NKV_ * D_];
__device__ __nv_bfloat16 g_kvlo[B_ * NKV_ * D_];
__device__ __nv_bfloat16 g_Wqhi[D_ * D_], g_Wqlo[D_ * D_];
__device__ __nv_bfloat16 g_Wkhi[D_ * D_], g_Wklo[D_ * D_];
__device__ __nv_bfloat16 g_Wvhi[D_ * D_], g_Wvlo[D_ * D_];
__device__ __nv_bfloat16 g_Wohi[D_ * D_], g_Wolo[D_ * D_];
__device__ __nv_bfloat16 g_Qhi[B_ * NQ_ * D_], g_Qlo[B_ * NQ_ * D_];
__device__ __nv_bfloat16 g_Khi[B_ * NKV_ * D_], g_Klo[B_ * NKV_ * D_];
__device__ __nv_bfloat16 g_Vhi[B_ * NKV_ * D_], g_Vlo[B_ * NKV_ * D_];
__device__ __nv_bfloat16 g_Ophi[B_ * NQ_ * D_], g_Oplo[B_ * NQ_ * D_];

__device__ __forceinline__ uint32_t smem_u32(const void* p) {
    uint32_t a;
    asm("{ .reg .u64 t; cvta.to.shared.u64 t, %1; cvt.u32.u64 %0, t; }"
        : "=r"(a) : "l"(p));
    return a;
}

__device__ __forceinline__ void mma_bf16(float* d, const uint32_t* a,
                                         uint32_t b0, uint32_t b1) {
    asm volatile(
        "mma.sync.aligned.m16n8k16.row.col.f32.bf16.bf16.f32 "
        "{%0,%1,%2,%3}, {%4,%5,%6,%7}, {%8,%9}, {%0,%1,%2,%3};"
        : "+f"(d[0]), "+f"(d[1]), "+f"(d[2]), "+f"(d[3])
        : "r"(a[0]), "r"(a[1]), "r"(a[2]), "r"(a[3]), "r"(b0), "r"(b1));
}

__device__ __forceinline__ void ldmx4(uint32_t* r, uint32_t addr) {
    asm volatile(
        "ldmatrix.sync.aligned.m8n8.x4.shared.b16 {%0,%1,%2,%3}, [%4];"
        : "=r"(r[0]), "=r"(r[1]), "=r"(r[2]), "=r"(r[3]) : "r"(addr));
}

__device__ __forceinline__ void ldmx4t(uint32_t* r, uint32_t addr) {
    asm volatile(
        "ldmatrix.sync.aligned.m8n8.x4.trans.shared.b16 {%0,%1,%2,%3}, [%4];"
        : "=r"(r[0]), "=r"(r[1]), "=r"(r[2]), "=r"(r[3]) : "r"(addr));
}

__device__ __forceinline__ uint32_t pack_bf16x2(float lo, float hi) {
    uint32_t r;
    asm("cvt.rn.bf16x2.f32 %0, %1, %2;" : "=r"(r) : "f"(hi), "f"(lo));
    return r;
}

#define CP16(dst, src) \
    asm volatile("cp.async.cg.shared.global [%0], [%1], 16;" :: "r"(dst), "l"(src))
#define CP_COMMIT() asm volatile("cp.async.commit_group;" ::: "memory")
#define CP_WAIT0()  asm volatile("cp.async.wait_group 0;" ::: "memory")

// ===========================================================================
// split: fp32 -> hi/lo bf16
// ===========================================================================
__global__ __launch_bounds__(256) void split_kernel(
    const float* __restrict__ x, __nv_bfloat16* __restrict__ hi,
    __nv_bfloat16* __restrict__ lo)
{
    const int i = (blockIdx.x * 256 + threadIdx.x) * 4;
    const float4 v = *(const float4*)(x + i);
    __nv_bfloat16 h0 = __float2bfloat16(v.x), h1 = __float2bfloat16(v.y);
    __nv_bfloat16 h2 = __float2bfloat16(v.z), h3 = __float2bfloat16(v.w);
    __nv_bfloat16 l0 = __float2bfloat16(v.x - __bfloat162float(h0));
    __nv_bfloat16 l1 = __float2bfloat16(v.y - __bfloat162float(h1));
    __nv_bfloat16 l2 = __float2bfloat16(v.z - __bfloat162float(h2));
    __nv_bfloat16 l3 = __float2bfloat16(v.w - __bfloat162float(h3));
    __nv_bfloat162 hp0, hp1, lp0, lp1;
    hp0.x = h0; hp0.y = h1; hp1.x = h2; hp1.y = h3;
    lp0.x = l0; lp0.y = l1; lp1.x = l2; lp1.y = l3;
    uint2 hv, lv;
    hv.x = *(uint32_t*)&hp0; hv.y = *(uint32_t*)&hp1;
    lv.x = *(uint32_t*)&lp0; lv.y = *(uint32_t*)&lp1;
    *(uint2*)(hi + i) = hv;
    *(uint2*)(lo + i) = lv;
}

// ===========================================================================
// Pre-split HMMA GEMM: C = A[M,K] @ W[N,K]^T + bias (bf16x3).
// CTA 128x128, K-chunk 64, double-buffered cp.async.
// 512 threads / 16 warps (4x4), warp tile 32x32 -> 4 warps per SMSP.
// ===========================================================================
#define GM 4096
#define GN 1024
#define GK 1024
#define PITCH_B 144
#define GT  (128 * PITCH_B)      // 18432 per tile
#define GST (4 * GT)             // 73728 per stage
#define SM_TOTAL (2 * GST)       // 147456

template <int OUTMODE>
__global__ __launch_bounds__(512) void gemm_ps(
    const __nv_bfloat16* __restrict__ Ahi, const __nv_bfloat16* __restrict__ Alo,
    const __nv_bfloat16* __restrict__ Whi, const __nv_bfloat16* __restrict__ Wlo,
    const float* __restrict__ bias, float* __restrict__ C,
    __nv_bfloat16* __restrict__ Chi, __nv_bfloat16* __restrict__ Clo,
    float scale)
{
    extern __shared__ char smem[];
    const uint32_t sb = smem_u32(smem);
    const int tid  = threadIdx.x;
    const int wid  = tid >> 5;
    const int lane = tid & 31;
    const int bm = blockIdx.y * 128;
    const int bn = blockIdx.x * 128;
    const int warp_m = wid >> 2;         // 0..3
    const int warp_n = wid & 3;          // 0..3

    float acc[2][4][4];
#pragma unroll
    for (int i = 0; i < 2; i++)
#pragma unroll
        for (int j = 0; j < 4; j++)
#pragma unroll
            for (int k = 0; k < 4; k++) acc[i][j][k] = 0.f;

    auto issue_chunk = [&](int chunk) {
        const uint32_t base = sb + (uint32_t)((chunk & 1) * GST);
        const int kc = chunk * 64;
#pragma unroll
        for (int it = 0; it < 8; it++) {
            const int t   = it >> 1;                // tile: Ahi,Alo,Whi,Wlo
            const int sub = (it & 1) * 512 + tid;   // 0..1023
            const int r   = sub >> 3;               // 0..127
            const int c   = sub & 7;                // 16B chunk in row
            const uint32_t dst = base + (uint32_t)(t * GT + r * PITCH_B + c * 16);
            const __nv_bfloat16* src;
            if      (t == 0) src = Ahi + (long)(bm + r) * GK + kc + c * 8;
            else if (t == 1) src = Alo + (long)(bm + r) * GK + kc + c * 8;
            else if (t == 2) src = Whi + (long)(bn + r) * GK + kc + c * 8;
            else             src = Wlo + (long)(bn + r) * GK + kc + c * 8;
            CP16(dst, src);
        }
        CP_COMMIT();
    };

    issue_chunk(0);

    for (int chunk = 0; chunk < GK / 64; chunk++) {
        CP_WAIT0();
        __syncthreads();
        if (chunk + 1 < GK / 64) issue_chunk(chunk + 1);

        const uint32_t base = sb + (uint32_t)((chunk & 1) * GST);
#pragma unroll
        for (int ks = 0; ks < 4; ks++) {
            uint32_t ah[2][4], al[2][4];
#pragma unroll
            for (int mt = 0; mt < 2; mt++) {
                const uint32_t ra = (uint32_t)((warp_m * 32 + mt * 16 + (lane & 15)) * PITCH_B
                                  + ks * 32 + (lane >> 4) * 16);
                ldmx4(ah[mt], base + ra);
                ldmx4(al[mt], base + GT + ra);
            }
            uint32_t bh[2][4], bl[2][4];
#pragma unroll
            for (int nt2 = 0; nt2 < 2; nt2++) {
                const uint32_t rb = (uint32_t)((warp_n * 32 + nt2 * 16 + (lane & 15)) * PITCH_B
                                  + ks * 32 + (lane >> 4) * 16);
                ldmx4(bh[nt2], base + 2 * GT + rb);
                ldmx4(bl[nt2], base + 3 * GT + rb);
            }
#pragma unroll
            for (int mt = 0; mt < 2; mt++) {
#pragma unroll
                for (int nt = 0; nt < 4; nt++) {
                    const int g = nt >> 1, o = nt & 1;
                    mma_bf16(acc[mt][nt], ah[mt], bh[g][o], bh[g][o + 2]);
                    mma_bf16(acc[mt][nt], ah[mt], bl[g][o], bl[g][o + 2]);
                    mma_bf16(acc[mt][nt], al[mt], bh[g][o], bh[g][o + 2]);
                }
            }
        }
    }

    const int rq = lane >> 2;
    const int cq = (lane & 3) * 2;
#pragma unroll
    for (int mt = 0; mt < 2; mt++) {
        const int r0 = bm + warp_m * 32 + mt * 16 + rq;
#pragma unroll
        for (int nt = 0; nt < 4; nt++) {
            const int c = bn + warp_n * 32 + nt * 8 + cq;
            const float2 bv = *(const float2*)&bias[c];
            if (OUTMODE == 0) {
                float2 o0, o1;
                o0.x = acc[mt][nt][0] + bv.x;
                o0.y = acc[mt][nt][1] + bv.y;
                o1.x = acc[mt][nt][2] + bv.x;
                o1.y = acc[mt][nt][3] + bv.y;
                *(float2*)&C[(long)r0 * GN + c] = o0;
                *(float2*)&C[(long)(r0 + 8) * GN + c] = o1;
            } else {
                const float v0 = (acc[mt][nt][0] + bv.x) * scale;
                const float v1 = (acc[mt][nt][1] + bv.y) * scale;
                const float v2 = (acc[mt][nt][2] + bv.x) * scale;
                const float v3 = (acc[mt][nt][3] + bv.y) * scale;
                const float h0 = __bfloat162float(__float2bfloat16(v0));
                const float h1 = __bfloat162float(__float2bfloat16(v1));
                const float h2 = __bfloat162float(__float2bfloat16(v2));
                const float h3 = __bfloat162float(__float2bfloat16(v3));
                *(uint32_t*)&Chi[(long)r0 * GN + c]       = pack_bf16x2(v0, v1);
                *(uint32_t*)&Chi[(long)(r0 + 8) * GN + c] = pack_bf16x2(v2, v3);
                *(uint32_t*)&Clo[(long)r0 * GN + c]       = pack_bf16x2(v0 - h0, v1 - h1);
                *(uint32_t*)&Clo[(long)(r0 + 8) * GN + c] = pack_bf16x2(v2 - h2, v3 - h3);
            }
        }
    }
}

// ===========================================================================
// HMMA flash attention (unchanged from R10). 64 q-rows, 4 warps, KV tiles
// of 64 double-buffered, Q overlaid on stage 1, split bf16 output.
// ===========================================================================
#define FPITCH 144
#define FT  (64 * FPITCH)
#define FST (4 * FT)
#define FSM_QHI (FST)
#define FSM_QLO (FST + FT)
#define FSM_TOTAL (2 * FST)        // 73728

__global__ __launch_bounds__(128) void flash_mma(
    const __nv_bfloat16* __restrict__ Qhi, const __nv_bfloat16* __restrict__ Qlo,
    const __nv_bfloat16* __restrict__ Khi, const __nv_bfloat16* __restrict__ Klo,
    const __nv_bfloat16* __restrict__ Vhi, const __nv_bfloat16* __restrict__ Vlo,
    __nv_bfloat16* __restrict__ Ophi, __nv_bfloat16* __restrict__ Oplo)
{
    extern __shared__ char smem[];
    const uint32_t sb = smem_u32(smem);
    const int tid  = threadIdx.x;
    const int wid  = tid >> 5;
    const int lane = tid & 31;
    const int qt = blockIdx.x, h = blockIdx.y, b = blockIdx.z;

    const long qrow0 = (long)b * NQ_ + qt * 64;
    const long krow0 = (long)b * NKV_;
    const int  col0  = h * DH_;

    auto issueKV = [&](int kt) {
        const uint32_t base = sb + (uint32_t)((kt & 1) * FST);
#pragma unroll
        for (int it = 0; it < 4; it++) {
            const int idx = it * 128 + tid;
            const int r = idx >> 3, c = idx & 7;
            const uint32_t doff = (uint32_t)(r * FPITCH + c * 16);
            const long goff = (krow0 + kt * 64 + r) * D_ + col0 + c * 8;
            CP16(base + doff,          Khi + goff);
            CP16(base + FT + doff,     Klo + goff);
            CP16(base + 2 * FT + doff, Vhi + goff);
            CP16(base + 3 * FT + doff, Vlo + goff);
        }
        CP_COMMIT();
    };

#pragma unroll
    for (int it = 0; it < 4; it++) {
        const int idx = it * 128 + tid;
        const int r = idx >> 3, c = idx & 7;
        const uint32_t doff = (uint32_t)(r * FPITCH + c * 16);
        const long goff = (qrow0 + r) * D_ + col0 + c * 8;
        CP16(sb + FSM_QHI + doff, Qhi + goff);
        CP16(sb + FSM_QLO + doff, Qlo + goff);
    }
    issueKV(0);
    CP_WAIT0();
    __syncthreads();

    const int m0 = wid * 16;
    uint32_t qh[4][4], ql[4][4];
#pragma unroll
    for (int ks = 0; ks < 4; ks++) {
        const uint32_t ra = (uint32_t)((m0 + (lane & 15)) * FPITCH + ks * 32 + (lane >> 4) * 16);
        ldmx4(qh[ks], sb + FSM_QHI + ra);
        ldmx4(ql[ks], sb + FSM_QLO + ra);
    }

    float o[8][4];
#pragma unroll
    for (int i = 0; i < 8; i++)
#pragma unroll
        for (int j = 0; j < 4; j++) o[i][j] = 0.f;
    float mr0 = -1e30f, mr1 = -1e30f, lr0 = 0.f, lr1 = 0.f;

    const int NT = NKV_ / 64;
    for (int kt = 0; kt < NT; kt++) {
        CP_WAIT0();
        __syncthreads();
        if (kt + 1 < NT) issueKV(kt + 1);

        const uint32_t kb = sb + (uint32_t)((kt & 1) * FST);

        float s[8][4];
#pragma unroll
        for (int i = 0; i < 8; i++)
#pragma unroll
            for (int j = 0; j < 4; j++) s[i][j] = 0.f;

#pragma unroll
        for (int ks = 0; ks < 4; ks++) {
#pragma unroll
            for (int ntp = 0; ntp < 4; ntp++) {
                const uint32_t rb = (uint32_t)((ntp * 16 + (lane & 15)) * FPITCH
                                  + ks * 32 + (lane >> 4) * 16);
                uint32_t bh[4], bl[4];
                ldmx4(bh, kb + rb);
                ldmx4(bl, kb + FT + rb);
#pragma unroll
                for (int oo = 0; oo < 2; oo++) {
                    float* d = s[ntp * 2 + oo];
                    mma_bf16(d, qh[ks], bh[oo], bh[oo + 2]);
                    mma_bf16(d, qh[ks], bl[oo], bl[oo + 2]);
                    mma_bf16(d, ql[ks], bh[oo], bh[oo + 2]);
                }
            }
        }

        float tm0 = -1e30f, tm1 = -1e30f;
#pragma unroll
        for (int i = 0; i < 8; i++) {
            tm0 = fmaxf(tm0, fmaxf(s[i][0], s[i][1]));
            tm1 = fmaxf(tm1, fmaxf(s[i][2], s[i][3]));
        }
        tm0 = fmaxf(tm0, __shfl_xor_sync(0xffffffffu, tm0, 1));
        tm0 = fmaxf(tm0, __shfl_xor_sync(0xffffffffu, tm0, 2));
        tm1 = fmaxf(tm1, __shfl_xor_sync(0xffffffffu, tm1, 1));
        tm1 = fmaxf(tm1, __shfl_xor_sync(0xffffffffu, tm1, 2));

        const float mn0 = fmaxf(mr0, tm0);
        const float mn1 = fmaxf(mr1, tm1);
        const float cr0 = __expf(mr0 - mn0);
        const float cr1 = __expf(mr1 - mn1);
        mr0 = mn0; mr1 = mn1;

        float ps0 = 0.f, ps1 = 0.f;
#pragma unroll
        for (int i = 0; i < 8; i++) {
            s[i][0] = __expf(s[i][0] - mn0);
            s[i][1] = __expf(s[i][1] - mn0);
            s[i][2] = __expf(s[i][2] - mn1);
            s[i][3] = __expf(s[i][3] - mn1);
            ps0 += s[i][0] + s[i][1];
            ps1 += s[i][2] + s[i][3];
        }
        ps0 += __shfl_xor_sync(0xffffffffu, ps0, 1);
        ps0 += __shfl_xor_sync(0xffffffffu, ps0, 2);
        ps1 += __shfl_xor_sync(0xffffffffu, ps1, 1);
        ps1 += __shfl_xor_sync(0xffffffffu, ps1, 2);
        lr0 = lr0 * cr0 + ps0;
        lr1 = lr1 * cr1 + ps1;

#pragma unroll
        for (int i = 0; i < 8; i++) {
            o[i][0] *= cr0; o[i][1] *= cr0;
            o[i][2] *= cr1; o[i][3] *= cr1;
        }

#pragma unroll
        for (int ks2 = 0; ks2 < 4; ks2++) {
            const int n0 = 2 * ks2, n1 = 2 * ks2 + 1;
            uint32_t ph[4], pl[4];
            float rv[8];
#pragma unroll
            for (int e = 0; e < 4; e++) {
                const float v0 = s[n0][e], v1 = s[n1][e];
                rv[e]     = v0 - __bfloat162float(__float2bfloat16(v0));
                rv[e + 4] = v1 - __bfloat162float(__float2bfloat16(v1));
            }
            ph[0] = pack_bf16x2(s[n0][0], s[n0][1]);
            ph[1] = pack_bf16x2(s[n0][2], s[n0][3]);
            ph[2] = pack_bf16x2(s[n1][0], s[n1][1]);
            ph[3] = pack_bf16x2(s[n1][2], s[n1][3]);
            pl[0] = pack_bf16x2(rv[0], rv[1]);
            pl[1] = pack_bf16x2(rv[2], rv[3]);
            pl[2] = pack_bf16x2(rv[4], rv[5]);
            pl[3] = pack_bf16x2(rv[6], rv[7]);

#pragma unroll
            for (int ntp = 0; ntp < 4; ntp++) {
                const uint32_t rv2 = (uint32_t)((ks2 * 16 + (lane & 15)) * FPITCH
                                   + ntp * 32 + (lane >> 4) * 16);
                uint32_t vh[4], vl[4];
                ldmx4t(vh, kb + 2 * FT + rv2);
                ldmx4t(vl, kb + 3 * FT + rv2);
#pragma unroll
                for (int o2 = 0; o2 < 2; o2++) {
                    float* d = o[ntp * 2 + o2];
                    mma_bf16(d, ph, vh[o2 * 2], vh[o2 * 2 + 1]);
                    mma_bf16(d, ph, vl[o2 * 2], vl[o2 * 2 + 1]);
                    mma_bf16(d, pl, vh[o2 * 2], vh[o2 * 2 + 1]);
                }
            }
        }
    }

    const float inv0 = 1.f / lr0;
    const float inv1 = 1.f / lr1;
    const int r = lane >> 2;
    const long orow = (qrow0 + m0 + r) * D_ + col0;
#pragma unroll
    for (int nt = 0; nt < 8; nt++) {
        const int c = nt * 8 + (lane & 3) * 2;
        const float a0 = o[nt][0] * inv0, a1 = o[nt][1] * inv0;
        const float a2 = o[nt][2] * inv1, a3 = o[nt][3] * inv1;
        const float h0 = __bfloat162float(__float2bfloat16(a0));
        const float h1 = __bfloat162float(__float2bfloat16(a1));
        const float h2 = __bfloat162float(__float2bfloat16(a2));
        const float h3 = __bfloat162float(__float2bfloat16(a3));
        *(uint32_t*)&Ophi[orow + c]           = pack_bf16x2(a0, a1);
        *(uint32_t*)&Ophi[orow + 8 * D_ + c]  = pack_bf16x2(a2, a3);
        *(uint32_t*)&Oplo[orow + c]           = pack_bf16x2(a0 - h0, a1 - h1);
        *(uint32_t*)&Oplo[orow + 8 * D_ + c]  = pack_bf16x2(a2 - h2, a3 - h3);
    }
}

// ===========================================================================
extern "C" void kernel_launch(void* const* d_in, const int* in_sizes, int n_in,
                              void* d_out, int out_size)
{
    const float* q  = (const float*)d_in[0];
    const float* kv = (const float*)d_in[1];
    const float* Wq = (const float*)d_in[2];
    const float* bq = (const float*)d_in[3];
    const float* Wk = (const float*)d_in[4];
    const float* bk = (const float*)d_in[5];
    const float* Wv = (const float*)d_in[6];
    const float* bv = (const float*)d_in[7];
    const float* Wo = (const float*)d_in[8];
    const float* bo = (const float*)d_in[9];
    float* out = (float*)d_out;

    __nv_bfloat16 *qhi, *qlo, *kvhi, *kvlo;
    __nv_bfloat16 *Wqhi, *Wqlo, *Wkhi, *Wklo, *Wvhi, *Wvlo, *Wohi, *Wolo;
    __nv_bfloat16 *Qhi, *Qlo, *Khi, *Klo, *Vhi, *Vlo, *Ophi, *Oplo;
    cudaGetSymbolAddress((void**)&qhi,  g_qhi);
    cudaGetSymbolAddress((void**)&qlo,  g_qlo);
    cudaGetSymbolAddress((void**)&kvhi, g_kvhi);
    cudaGetSymbolAddress((void**)&kvlo, g_kvlo);
    cudaGetSymbolAddress((void**)&Wqhi, g_Wqhi);
    cudaGetSymbolAddress((void**)&Wqlo, g_Wqlo);
    cudaGetSymbolAddress((void**)&Wkhi, g_Wkhi);
    cudaGetSymbolAddress((void**)&Wklo, g_Wklo);
    cudaGetSymbolAddress((void**)&Wvhi, g_Wvhi);
    cudaGetSymbolAddress((void**)&Wvlo, g_Wvlo);
    cudaGetSymbolAddress((void**)&Wohi, g_Wohi);
    cudaGetSymbolAddress((void**)&Wolo, g_Wolo);
    cudaGetSymbolAddress((void**)&Qhi,  g_Qhi);
    cudaGetSymbolAddress((void**)&Qlo,  g_Qlo);
    cudaGetSymbolAddress((void**)&Khi,  g_Khi);
    cudaGetSymbolAddress((void**)&Klo,  g_Klo);
    cudaGetSymbolAddress((void**)&Vhi,  g_Vhi);
    cudaGetSymbolAddress((void**)&Vlo,  g_Vlo);
    cudaGetSymbolAddress((void**)&Ophi, g_Ophi);
    cudaGetSymbolAddress((void**)&Oplo, g_Oplo);

    cudaFuncSetAttribute(gemm_ps<0>, cudaFuncAttributeMaxDynamicSharedMemorySize, SM_TOTAL);
    cudaFuncSetAttribute(gemm_ps<1>, cudaFuncAttributeMaxDynamicSharedMemorySize, SM_TOTAL);
    cudaFuncSetAttribute(flash_mma,  cudaFuncAttributeMaxDynamicSharedMemorySize, FSM_TOTAL);

    const int NQK = B_ * NQ_ * D_;
    const int NW  = D_ * D_;
    split_kernel<<<NQK / 1024, 256>>>(q,  qhi,  qlo);
    split_kernel<<<NQK / 1024, 256>>>(kv, kvhi, kvlo);
    split_kernel<<<NW / 1024, 256>>>(Wq, Wqhi, Wqlo);
    split_kernel<<<NW / 1024, 256>>>(Wk, Wkhi, Wklo);
    split_kernel<<<NW / 1024, 256>>>(Wv, Wvhi, Wvlo);
    split_kernel<<<NW / 1024, 256>>>(Wo, Wohi, Wolo);

    dim3 ggrid(GN / 128, GM / 128);  // (8, 32)

    gemm_ps<1><<<ggrid, 512, SM_TOTAL>>>(qhi,  qlo,  Wqhi, Wqlo, bq, nullptr, Qhi, Qlo, 0.125f);
    gemm_ps<1><<<ggrid, 512, SM_TOTAL>>>(kvhi, kvlo, Wkhi, Wklo, bk, nullptr, Khi, Klo, 1.0f);
    gemm_ps<1><<<ggrid, 512, SM_TOTAL>>>(kvhi, kvlo, Wvhi, Wvlo, bv, nullptr, Vhi, Vlo, 1.0f);

    flash_mma<<<dim3(NQ_ / 64, H_, B_), 128, FSM_TOTAL>>>(Qhi, Qlo, Khi, Klo, Vhi, Vlo, Ophi, Oplo);

    gemm_ps<0><<<ggrid, 512, SM_TOTAL>>>(Ophi, Oplo, Wohi, Wolo, bo, out, nullptr, nullptr, 1.0f);
}